// round 6
// baseline (speedup 1.0000x reference)
#include <cuda_runtime.h>
#include <cuda_fp16.h>
#include <math.h>
#include <stdint.h>

#define BB   32
#define TT   512
#define SS   512
#define DD   1024
#define MM   10
#define K3   3072
#define KP   3080      // padded K stride (halves) for Ws: conflict-free B-frag loads
#define NCTA 128
#define NTHR 256

// ---------------- static device scratch (allocations are forbidden) ----------------
__device__ __half  g_in[BB * TT * DD];          // fp16 copy of input_h_c
__device__ __half  g_mem[BB * SS * DD];         // fp16 copy of memory
__device__ __half  g_ctx[BB * DD];              // ctx_t (fp16), produced by phase C
__device__ __half  g_h[2][BB * DD];             // double-buffered h (fp16)
__device__ float   g_phipart[2][NCTA][BB][32];  // per-CTA phi partials, dbl-buffered
__device__ unsigned g_arrive[NCTA];             // flag barrier: per-CTA arrival
__device__ unsigned g_cctr;                     // phase-C completion counter (monotonic)

// ---------------- dynamic shared memory layout ----------------
struct Smem {
    __half Ws[32][KP];                 // persistent weight slice     197120 B
    union {
        __half xsw[8][2][16][40];      // per-warp x staging           20480 B
        float  redA[4][2][16][33];     // K-split reduction            16896 B
        float  cred[8][256];           // phase-C cross-warp reduce     8192 B
    } u;
    float gates[32][32];               // reduced gate tile             4096 B
    float cst[32][8];                  // persistent cell state         1024 B
    float hs[32][8];                   // fp32 h slice                  1024 B
    float Wg[32][8];                   // W_g slice (30 used)           1024 B
    float biasv[32];                   // b_ih + b_hh per local col      128 B
    float bgs[32];                     // b_g (30 used)                  128 B
    float predbuf[8][32];              // phi reduce stage               1024 B
    float phired[32];                  // reduced phi (30 used)           128 B
    float wbuf[SS];                    // attention weights              2048 B
    float Fbuf[520];                   // telescoped CDF F(s), s=-1..511 2080 B
    float ksi[16];                     // persistent ksi                   64 B
    float rbeta[16];                   // 1/beta                           64 B
    float alpha[16];                   // softmax alpha                    64 B
    int   winlo, winhi;                // phase-C window                    8 B
};

// ---------------- all-poll grid barrier (128 CTAs co-resident) ----------------
// Each CTA publishes its monotonically increasing arrival; every CTA polls all
// 128 flags directly (no central release round trip).
__device__ __forceinline__ void allpollbar(int cta, int tid, unsigned want) {
    __syncthreads();
    if (tid == 0) {
        __threadfence();
        *(volatile unsigned*)&g_arrive[cta] = want;
    }
    if (tid < NCTA) {
        while (*(volatile unsigned*)&g_arrive[tid] < want) { }
    }
    __syncthreads();
}

// ---------------- prep: fp32 -> fp16 conversions + state reset ----------------
__global__ void tts_prep(const float* __restrict__ in, const float* __restrict__ mem) {
    const int tid = blockIdx.x * blockDim.x + threadIdx.x;
    const int np  = gridDim.x * blockDim.x;
    const int N1  = BB * TT * DD;
    for (int i = tid; i < N1; i += np) g_in[i]  = __float2half(in[i]);
    for (int i = tid; i < N1; i += np) g_mem[i] = __float2half(mem[i]);
    for (int i = tid; i < BB * DD; i += np) {
        g_ctx[i]  = __float2half(0.f);
        g_h[0][i] = __float2half(0.f);
        g_h[1][i] = __float2half(0.f);
    }
    if (tid < NCTA) g_arrive[tid] = 0u;
    if (tid == 0) g_cctr = 0u;
}

#define MMA_16816(ac, A0, A1, A2, A3, B0, B1)                               \
    asm volatile(                                                           \
        "mma.sync.aligned.m16n8k16.row.col.f32.f16.f16.f32 "                \
        "{%0,%1,%2,%3}, {%4,%5,%6,%7}, {%8,%9}, {%0,%1,%2,%3};"             \
        : "+f"((ac)[0]), "+f"((ac)[1]), "+f"((ac)[2]), "+f"((ac)[3])        \
        : "r"(A0), "r"(A1), "r"(A2), "r"(A3), "r"(B0), "r"(B1))

__device__ __forceinline__ float sigf(float x) {
    return __fdividef(1.f, 1.f + __expf(-x));
}

// ---------------- main persistent kernel ----------------
__global__ void __launch_bounds__(NTHR, 1) tts_main(
    const float* __restrict__ W_ih, const float* __restrict__ W_hh,
    const float* __restrict__ b_ih, const float* __restrict__ b_hh,
    const float* __restrict__ W_g,  const float* __restrict__ b_g,
    const int*   __restrict__ lens, float* __restrict__ out)
{
    extern __shared__ char smraw[];
    Smem& sm = *reinterpret_cast<Smem*>(smraw);
    const int tid  = threadIdx.x;
    const int cta  = blockIdx.x;
    const int wid  = tid >> 5;
    const int lane = tid & 31;

    const size_t ALIGN_OFF = (size_t)BB * DD;                      // 32768
    const size_t TERM_OFF  = ALIGN_OFF + (size_t)BB * TT * SS;     // 8421376

    // ---- one-time init ----
    for (int i = tid; i < 32 * K3; i += NTHR) {
        int c = i / K3, k = i - c * K3;
        int gcol = (c >> 3) * DD + cta * 8 + (c & 7);
        float wv = (k < 2048) ? W_ih[(size_t)gcol * 2048 + k]
                              : W_hh[(size_t)gcol * DD + (k - 2048)];
        sm.Ws[c][k] = __float2half(wv);
    }
    if (tid < 240) {
        int j = tid >> 3, uu = tid & 7;
        sm.Wg[j][uu] = W_g[(size_t)j * DD + cta * 8 + uu];
    }
    if (tid < 32) {
        int gcol = (tid >> 3) * DD + cta * 8 + (tid & 7);
        sm.biasv[tid] = b_ih[gcol] + b_hh[gcol];
    }
    if (tid < 30) sm.bgs[tid] = b_g[tid];
    { int b2 = tid >> 3, uu = tid & 7; sm.cst[b2][uu] = 0.f; }
    if (tid < 16) { sm.ksi[tid] = 0.f; sm.rbeta[tid] = 0.f; sm.alpha[tid] = 0.f; }
    __syncthreads();

    // warp roles for the gate GEMM
    const int bt = wid & 1;          // batch-half (rows bt*16 .. +16)
    const int kq = wid >> 1;         // K-quarter  (k in [kq*768, +768))
    const int gg = lane >> 2;        // mma group id (0..7)
    const int tg = lane & 3;         // thread-in-group (0..3)
    __half (&xw)[2][16][40] = sm.u.xsw[wid];
    const int xrow = lane >> 1;              // 0..15
    const int xb   = bt * 16 + xrow;         // global batch
    const int xo   = (lane & 1) * 16;        // half-offset within 32-half chunk
    // ctx region is k in [1024,2048): kq==1 chunks 8..23; kq==2 chunks 0..15
    // (remapped so h-chunks run first). First ctx chunk is always seq index 8.
    const bool needs_ctx = (kq == 1 || kq == 2);

    // phase B/C roles
    const int b  = cta & 31;     // batch
    const int dg = cta >> 5;     // d-slice (0..3) of 256

    for (int t = 0; t < TT; ++t) {
        const int p = t & 1;

        // ================= Phase A : gate GEMM =================
        float acc[16];
        #pragma unroll
        for (int i = 0; i < 16; ++i) acc[i] = 0.f;

        auto seqmap = [&](int i) -> int {
            return (kq == 2) ? ((i < 8) ? i + 16 : i - 8) : i;
        };
        auto xsrc = [&](int kc) -> const __half* {
            int kk = kq * 768 + kc * 32;
            if (kk < 1024) return g_in  + ((size_t)xb * TT + t) * DD + kk;
            if (kk < 2048) return g_ctx + xb * DD + (kk - 1024);
            return g_h[p] + xb * DD + (kk - 2048);
        };
        auto compute_chunk = [&](int buf, int kc) {
            const int k0 = kq * 768 + kc * 32;
            #pragma unroll
            for (int kt = 0; kt < 2; ++kt) {
                const int kb = kt * 16;
                unsigned a0 = *(const unsigned*)&xw[buf][gg    ][kb + 2 * tg];
                unsigned a1 = *(const unsigned*)&xw[buf][gg + 8][kb + 2 * tg];
                unsigned a2 = *(const unsigned*)&xw[buf][gg    ][kb + 2 * tg + 8];
                unsigned a3 = *(const unsigned*)&xw[buf][gg + 8][kb + 2 * tg + 8];
                const int kg = k0 + kb;
                #pragma unroll
                for (int nt = 0; nt < 4; ++nt) {
                    unsigned b0 = *(const unsigned*)&sm.Ws[nt * 8 + gg][kg + 2 * tg];
                    unsigned b1 = *(const unsigned*)&sm.Ws[nt * 8 + gg][kg + 2 * tg + 8];
                    MMA_16816(acc + nt * 4, a0, a1, a2, a3, b0, b1);
                }
            }
        };

        uint4 r0a, r0b, r1a, r1b;
        {   // prologue: seq0 -> buf0, seq1 -> r0, seq2 -> r1 (all non-ctx)
            const __half* sp = xsrc(seqmap(0));
            uint4 ta = __ldcg((const uint4*)(sp + xo));
            uint4 tb = __ldcg((const uint4*)(sp + xo + 8));
            *(uint4*)&xw[0][xrow][xo]     = ta;
            *(uint4*)&xw[0][xrow][xo + 8] = tb;
            sp  = xsrc(seqmap(1));
            r0a = __ldcg((const uint4*)(sp + xo));
            r0b = __ldcg((const uint4*)(sp + xo + 8));
            sp  = xsrc(seqmap(2));
            r1a = __ldcg((const uint4*)(sp + xo));
            r1b = __ldcg((const uint4*)(sp + xo + 8));
        }
        __syncwarp();

        #pragma unroll 1
        for (int i = 0; i < 24; i += 2) {
            // even slot: compute seq i from buf0
            compute_chunk(0, seqmap(i));
            *(uint4*)&xw[1][xrow][xo]     = r0a;     // stage seq i+1
            *(uint4*)&xw[1][xrow][xo + 8] = r0b;
            if (i + 3 < 24) {                         // prefetch seq i+3
                const __half* sp = xsrc(seqmap(i + 3));
                r0a = __ldcg((const uint4*)(sp + xo));
                r0b = __ldcg((const uint4*)(sp + xo + 8));
            }
            __syncwarp();
            // odd slot: compute seq i+1 from buf1
            compute_chunk(1, seqmap(i + 1));
            if (i + 2 < 24) {                         // stage seq i+2
                *(uint4*)&xw[0][xrow][xo]     = r1a;
                *(uint4*)&xw[0][xrow][xo + 8] = r1b;
            }
            if (i + 4 < 24) {                         // prefetch seq i+4
                if (needs_ctx && i == 4) {
                    // seq 8 is the first ctx chunk: wait for all CTAs' phase C
                    // of step t-1 before touching g_ctx.
                    const unsigned want = (unsigned)(NCTA * t);
                    while (*(volatile unsigned*)&g_cctr < want) { }
                    __threadfence();
                }
                const __half* sp = xsrc(seqmap(i + 4));
                r1a = __ldcg((const uint4*)(sp + xo));
                r1b = __ldcg((const uint4*)(sp + xo + 8));
            }
            __syncwarp();
        }
        __syncthreads();

        // K-split reduction: store frags, reduce over kq in fixed order
        #pragma unroll
        for (int nt = 0; nt < 4; ++nt) {
            #pragma unroll
            for (int i = 0; i < 4; ++i) {
                int r = gg + ((i >> 1) << 3);
                int c = nt * 8 + tg * 2 + (i & 1);
                sm.u.redA[kq][bt][r][c] = acc[nt * 4 + i];
            }
        }
        __syncthreads();
        #pragma unroll
        for (int rep = 0; rep < 4; ++rep) {
            int f = tid + rep * 256;               // 0..1023
            int bt2 = f >> 9, q = f & 511, r = q >> 5, c = q & 31;
            float v = sm.u.redA[0][bt2][r][c] + sm.u.redA[1][bt2][r][c]
                    + sm.u.redA[2][bt2][r][c] + sm.u.redA[3][bt2][r][c];
            sm.gates[bt2 * 16 + r][c] = v;
        }
        __syncthreads();

        // ---- LSTM cell (thread = (batch, unit)) ----
        {
            int bb = tid >> 3, uu = tid & 7;
            float ig = sm.gates[bb][uu]      + sm.biasv[uu];
            float fg = sm.gates[bb][8 + uu]  + sm.biasv[8 + uu];
            float gv = sm.gates[bb][16 + uu] + sm.biasv[16 + uu];
            float og = sm.gates[bb][24 + uu] + sm.biasv[24 + uu];
            float cn = sigf(fg) * sm.cst[bb][uu] + sigf(ig) * tanhf(gv);
            sm.cst[bb][uu] = cn;
            float hv = sigf(og) * tanhf(cn);
            sm.hs[bb][uu] = hv;
            g_h[p ^ 1][bb * DD + cta * 8 + uu] = __float2half(hv);
        }
        __syncthreads();

        // ---- phi partials over this CTA's 8 units (double-buffered by t&1) ----
        #pragma unroll
        for (int it = 0; it < 4; ++it) {
            int idx = tid + it * 256;
            if (idx < 960) {
                int pb = idx / 30, j = idx - pb * 30;
                float s = 0.f;
                #pragma unroll
                for (int uu = 0; uu < 8; ++uu) s += sm.hs[pb][uu] * sm.Wg[j][uu];
                g_phipart[p][cta][pb][j] = s;
            }
        }

        allpollbar(cta, tid, (unsigned)(t + 1));   // phi + h visible everywhere

        // ================= Phase B : mixture head (batch b) =================
        if (tid < 240) {
            int j = tid % 30, cg = tid / 30;
            float s = 0.f;
            int c0 = cg * 16;
            #pragma unroll
            for (int c = 0; c < 16; ++c) s += __ldcg(&g_phipart[p][c0 + c][b][j]);
            sm.predbuf[cg][j] = s;
        }
        __syncthreads();
        if (tid < 30) {
            float s = sm.bgs[tid];
            #pragma unroll
            for (int cg = 0; cg < 8; ++cg) s += sm.predbuf[cg][tid];
            sm.phired[tid] = s;
        }
        __syncthreads();

        // mixture params + dynamic window, parallel over 10 lanes of warp 0
        if (wid == 0) {
            float pha = (lane < MM) ? sm.phired[20 + lane] : -1e30f;
            float mx = pha;
            #pragma unroll
            for (int off = 16; off >= 1; off >>= 1)
                mx = fmaxf(mx, __shfl_xor_sync(0xffffffffu, mx, off));
            float e = (lane < MM) ? __expf(pha - mx) : 0.f;
            float ssum = e;
            #pragma unroll
            for (int off = 16; off >= 1; off >>= 1)
                ssum += __shfl_xor_sync(0xffffffffu, ssum, off);
            float kv = 0.f, beta = 0.f;
            if (lane < MM) {
                float phb = sm.phired[10 + lane];
                kv   = sm.ksi[lane] + __expf(sm.phired[lane]);
                beta = __expf(phb);
                sm.ksi[lane]   = kv;
                sm.rbeta[lane] = __expf(-phb);
                sm.alpha[lane] = __fdividef(e, ssum);
            }
            float lof = (lane < MM) ? (kv - 14.f * beta - 1.5f) :  1e30f;
            float hif = (lane < MM) ? (kv + 14.f * beta + 0.5f) : -1e30f;
            #pragma unroll
            for (int off = 16; off >= 1; off >>= 1) {
                lof = fminf(lof, __shfl_xor_sync(0xffffffffu, lof, off));
                hif = fmaxf(hif, __shfl_xor_sync(0xffffffffu, hif, off));
            }
            if (lane == 0) {
                int lo = (int)floorf(lof); if (lo < 0) lo = 0; if (lo > SS) lo = SS;
                int hi = (int)ceilf(hif) + 1; if (hi > SS) hi = SS; if (hi < lo) hi = lo;
                sm.winlo = lo; sm.winhi = hi;
            }
        }
        __syncthreads();

        // telescoped CDF: Fbuf[idx] = F(idx-1), idx = 0..512
        #pragma unroll
        for (int rep = 0; rep < 3; ++rep) {
            int idx = tid + rep * 256;
            if (idx < 513) {
                float su = (float)(idx - 1);
                float F = 0.f;
                #pragma unroll
                for (int m = 0; m < MM; ++m)
                    F += sm.alpha[m] * sigf((su + 1.5f - sm.ksi[m]) * sm.rbeta[m]);
                sm.Fbuf[idx] = F;
            }
        }
        __syncthreads();

        // w[s] = F(s) - F(s-1); write alignment for this step
        #pragma unroll
        for (int rep = 0; rep < 2; ++rep) {
            int s = tid + rep * 256;
            float w = sm.Fbuf[s + 1] - sm.Fbuf[s];
            sm.wbuf[s] = w;
            if (dg == 0) out[ALIGN_OFF + ((size_t)b * TT + t) * SS + s] = w;
        }
        // termination (last step): 1 - F(len-1)
        if (t == TT - 1 && dg == 0 && tid == 0) {
            int sl = lens[b] - 1;
            out[TERM_OFF + b] = 1.f - sm.Fbuf[sl + 1];
        }
        __syncthreads();

        // ================= Phase C : ctx = w @ memory (windowed) =================
        {
            const int lo = sm.winlo, hi = sm.winhi;
            float accv[8];
            #pragma unroll
            for (int j = 0; j < 8; ++j) accv[j] = 0.f;
            const __half* mpb = g_mem + (size_t)b * SS * DD + dg * 256 + lane * 8;
            // warp wid covers s ≡ lo+wid (mod 8); 4-deep load batching for MLP
            for (int s0 = lo + wid; s0 < hi; s0 += 32) {
                uint4 v[4]; float wv[4];
                #pragma unroll
                for (int j = 0; j < 4; ++j) {
                    int s = s0 + 8 * j;
                    if (s < hi) {
                        v[j]  = __ldg((const uint4*)(mpb + (size_t)s * DD));
                        wv[j] = sm.wbuf[s];
                    }
                }
                #pragma unroll
                for (int j = 0; j < 4; ++j) {
                    int s = s0 + 8 * j;
                    if (s < hi) {
                        const __half2* h2 = (const __half2*)&v[j];
                        #pragma unroll
                        for (int q = 0; q < 4; ++q) {
                            float2 f = __half22float2(h2[q]);
                            accv[2 * q]     += wv[j] * f.x;
                            accv[2 * q + 1] += wv[j] * f.y;
                        }
                    }
                }
            }
            float* cr = sm.u.cred[wid];
            #pragma unroll
            for (int j = 0; j < 8; ++j) cr[lane * 8 + j] = accv[j];
        }
        __syncthreads();
        {
            int d = tid;                       // 0..255 within this CTA's d-slice
            float s0 = 0.f;
            #pragma unroll
            for (int w = 0; w < 8; ++w) s0 += sm.u.cred[w][d];
            g_ctx[b * DD + dg * 256 + d] = __float2half(s0);
            if (t == TT - 1) out[b * DD + dg * 256 + d] = s0;
        }
        __syncthreads();
        if (tid == 0) {
            __threadfence();
            atomicAdd(&g_cctr, 1u);            // phase-C completion (replaces barrier2)
        }
    }
}

extern "C" void kernel_launch(void* const* d_in, const int* in_sizes, int n_in,
                              void* d_out, int out_size) {
    const float* in_h   = (const float*)d_in[0];
    const float* mem    = (const float*)d_in[1];
    const int*   lens   = (const int*)d_in[2];
    const float* W_ih   = (const float*)d_in[3];
    const float* W_hh   = (const float*)d_in[4];
    const float* b_ih   = (const float*)d_in[5];
    const float* b_hh   = (const float*)d_in[6];
    const float* W_g    = (const float*)d_in[7];
    const float* b_g    = (const float*)d_in[8];
    float* out = (float*)d_out;

    cudaFuncSetAttribute(tts_main, cudaFuncAttributeMaxDynamicSharedMemorySize,
                         (int)sizeof(Smem));

    tts_prep<<<1024, 256>>>(in_h, mem);
    tts_main<<<NCTA, NTHR, sizeof(Smem)>>>(W_ih, W_hh, b_ih, b_hh, W_g, b_g, lens, out);
}

// round 7
// speedup vs baseline: 1.1918x; 1.1918x over previous
#include <cuda_runtime.h>
#include <cuda_fp16.h>
#include <math.h>
#include <stdint.h>

#define BB   32
#define TT   512
#define SS   512
#define DD   1024
#define MM   10
#define K3   3072
#define KP   3080      // padded K stride (halves) for Ws: conflict-free B-frag loads
#define NCTA 128
#define NTHR 256

// ---------------- static device scratch (allocations are forbidden) ----------------
__device__ __half  g_in[BB * TT * DD];          // fp16 copy of input_h_c
__device__ __half  g_mem[BB * SS * DD];         // fp16 copy of memory
__device__ __half  g_ctx[BB * DD];              // ctx_t (fp16), produced by phase C
__device__ __half  g_h[2][BB * DD];             // double-buffered h (fp16)
__device__ float   g_phipart[2][NCTA][BB][32];  // per-CTA phi partials, dbl-buffered
__device__ unsigned g_arrive[NCTA];             // flag barrier: per-CTA arrival
__device__ unsigned g_release;                  // flag barrier: release word
__device__ unsigned g_cctr;                     // phase-C completion counter (monotonic)

// ---------------- dynamic shared memory layout ----------------
struct Smem {
    __half Ws[32][KP];                 // persistent weight slice     197120 B
    union {
        __half xsw[8][2][16][40];      // per-warp x staging           20480 B
        float  redA[4][2][16][33];     // K-split reduction            16896 B
        float  cred[8][256];           // phase-C cross-warp reduce     8192 B
    } u;
    float gates[32][32];               // reduced gate tile             4096 B
    float cst[32][8];                  // persistent cell state         1024 B
    float hs[32][8];                   // fp32 h slice                  1024 B
    float Wg[32][8];                   // W_g slice (30 used)           1024 B
    float biasv[32];                   // b_ih + b_hh per local col      128 B
    float bgs[32];                     // b_g (30 used)                  128 B
    float predbuf[8][32];              // phi reduce stage               1024 B
    float phired[32];                  // reduced phi (30 used)           128 B
    float wbuf[SS];                    // attention weights              2048 B
    float Fbuf[520];                   // telescoped CDF F(s), s=-1..511 2080 B
    float ksi[16];                     // persistent ksi                   64 B
    float rbeta[16];                   // 1/beta                           64 B
    float alpha[16];                   // softmax alpha                    64 B
    int   winlo, winhi;                // phase-C window                    8 B
};

// ---------------- flag + release grid barrier (R4-proven) ----------------
// Non-zero CTAs: write own flag, poll the single release word (one hot
// read-shared L2 line). CTA0: 128 threads poll the 128 flags in parallel,
// then one thread publishes the release word. Keeps poll fan-out small for
// 127 of 128 CTAs -> no L2 line ping-pong storm.
__device__ __forceinline__ void flagbar(int cta, int tid, unsigned want) {
    __syncthreads();
    if (cta == 0) {
        if (tid == 0) {
            __threadfence();
            *(volatile unsigned*)&g_arrive[0] = want;
        }
        if (tid < NCTA) {
            while (*(volatile unsigned*)&g_arrive[tid] < want) { }
        }
        __syncthreads();
        if (tid == 0) {
            __threadfence();
            *(volatile unsigned*)&g_release = want;
        }
    } else {
        if (tid == 0) {
            __threadfence();
            *(volatile unsigned*)&g_arrive[cta] = want;
            while (*(volatile unsigned*)&g_release < want) { }
            __threadfence();
        }
    }
    __syncthreads();
}

// ---------------- prep: fp32 -> fp16 conversions + state reset ----------------
__global__ void tts_prep(const float* __restrict__ in, const float* __restrict__ mem) {
    const int tid = blockIdx.x * blockDim.x + threadIdx.x;
    const int np  = gridDim.x * blockDim.x;
    const int N1  = BB * TT * DD;
    for (int i = tid; i < N1; i += np) g_in[i]  = __float2half(in[i]);
    for (int i = tid; i < N1; i += np) g_mem[i] = __float2half(mem[i]);
    for (int i = tid; i < BB * DD; i += np) {
        g_ctx[i]  = __float2half(0.f);
        g_h[0][i] = __float2half(0.f);
        g_h[1][i] = __float2half(0.f);
    }
    if (tid < NCTA) g_arrive[tid] = 0u;
    if (tid == 0) { g_release = 0u; g_cctr = 0u; }
}

#define MMA_16816(ac, A0, A1, A2, A3, B0, B1)                               \
    asm volatile(                                                           \
        "mma.sync.aligned.m16n8k16.row.col.f32.f16.f16.f32 "                \
        "{%0,%1,%2,%3}, {%4,%5,%6,%7}, {%8,%9}, {%0,%1,%2,%3};"             \
        : "+f"((ac)[0]), "+f"((ac)[1]), "+f"((ac)[2]), "+f"((ac)[3])        \
        : "r"(A0), "r"(A1), "r"(A2), "r"(A3), "r"(B0), "r"(B1))

__device__ __forceinline__ float sigf(float x) {
    return __fdividef(1.f, 1.f + __expf(-x));
}

// ---------------- main persistent kernel ----------------
__global__ void __launch_bounds__(NTHR, 1) tts_main(
    const float* __restrict__ W_ih, const float* __restrict__ W_hh,
    const float* __restrict__ b_ih, const float* __restrict__ b_hh,
    const float* __restrict__ W_g,  const float* __restrict__ b_g,
    const int*   __restrict__ lens, float* __restrict__ out)
{
    extern __shared__ char smraw[];
    Smem& sm = *reinterpret_cast<Smem*>(smraw);
    const int tid  = threadIdx.x;
    const int cta  = blockIdx.x;
    const int wid  = tid >> 5;
    const int lane = tid & 31;

    const size_t ALIGN_OFF = (size_t)BB * DD;                      // 32768
    const size_t TERM_OFF  = ALIGN_OFF + (size_t)BB * TT * SS;     // 8421376

    // ---- one-time init ----
    for (int i = tid; i < 32 * K3; i += NTHR) {
        int c = i / K3, k = i - c * K3;
        int gcol = (c >> 3) * DD + cta * 8 + (c & 7);
        float wv = (k < 2048) ? W_ih[(size_t)gcol * 2048 + k]
                              : W_hh[(size_t)gcol * DD + (k - 2048)];
        sm.Ws[c][k] = __float2half(wv);
    }
    if (tid < 240) {
        int j = tid >> 3, uu = tid & 7;
        sm.Wg[j][uu] = W_g[(size_t)j * DD + cta * 8 + uu];
    }
    if (tid < 32) {
        int gcol = (tid >> 3) * DD + cta * 8 + (tid & 7);
        sm.biasv[tid] = b_ih[gcol] + b_hh[gcol];
    }
    if (tid < 30) sm.bgs[tid] = b_g[tid];
    { int b2 = tid >> 3, uu = tid & 7; sm.cst[b2][uu] = 0.f; }
    if (tid < 16) { sm.ksi[tid] = 0.f; sm.rbeta[tid] = 0.f; sm.alpha[tid] = 0.f; }
    __syncthreads();

    // warp roles for the gate GEMM
    const int bt = wid & 1;          // batch-half (rows bt*16 .. +16)
    const int kq = wid >> 1;         // K-quarter  (k in [kq*768, +768))
    const int gg = lane >> 2;        // mma group id (0..7)
    const int tg = lane & 3;         // thread-in-group (0..3)
    __half (&xw)[2][16][40] = sm.u.xsw[wid];
    const int xrow = lane >> 1;              // 0..15
    const int xb   = bt * 16 + xrow;         // global batch
    const int xo   = (lane & 1) * 16;        // half-offset within 32-half chunk
    // ctx region is k in [1024,2048): kq==1 chunks 8..23; kq==2 chunks 0..15
    // (remapped so h-chunks run first). First ctx chunk is always seq index 8.
    const bool needs_ctx = (kq == 1 || kq == 2);

    // phase B/C roles
    const int b  = cta & 31;     // batch
    const int dg = cta >> 5;     // d-slice (0..3) of 256

    for (int t = 0; t < TT; ++t) {
        const int p = t & 1;

        // ================= Phase A : gate GEMM =================
        float acc[16];
        #pragma unroll
        for (int i = 0; i < 16; ++i) acc[i] = 0.f;

        auto seqmap = [&](int i) -> int {
            return (kq == 2) ? ((i < 8) ? i + 16 : i - 8) : i;
        };
        auto xsrc = [&](int kc) -> const __half* {
            int kk = kq * 768 + kc * 32;
            if (kk < 1024) return g_in  + ((size_t)xb * TT + t) * DD + kk;
            if (kk < 2048) return g_ctx + xb * DD + (kk - 1024);
            return g_h[p] + xb * DD + (kk - 2048);
        };
        auto compute_chunk = [&](int buf, int kc) {
            const int k0 = kq * 768 + kc * 32;
            #pragma unroll
            for (int kt = 0; kt < 2; ++kt) {
                const int kb = kt * 16;
                unsigned a0 = *(const unsigned*)&xw[buf][gg    ][kb + 2 * tg];
                unsigned a1 = *(const unsigned*)&xw[buf][gg + 8][kb + 2 * tg];
                unsigned a2 = *(const unsigned*)&xw[buf][gg    ][kb + 2 * tg + 8];
                unsigned a3 = *(const unsigned*)&xw[buf][gg + 8][kb + 2 * tg + 8];
                const int kg = k0 + kb;
                #pragma unroll
                for (int nt = 0; nt < 4; ++nt) {
                    unsigned b0 = *(const unsigned*)&sm.Ws[nt * 8 + gg][kg + 2 * tg];
                    unsigned b1 = *(const unsigned*)&sm.Ws[nt * 8 + gg][kg + 2 * tg + 8];
                    MMA_16816(acc + nt * 4, a0, a1, a2, a3, b0, b1);
                }
            }
        };

        uint4 r0a, r0b, r1a, r1b;
        {   // prologue: seq0 -> buf0, seq1 -> r0, seq2 -> r1 (all non-ctx)
            const __half* sp = xsrc(seqmap(0));
            uint4 ta = __ldcg((const uint4*)(sp + xo));
            uint4 tb = __ldcg((const uint4*)(sp + xo + 8));
            *(uint4*)&xw[0][xrow][xo]     = ta;
            *(uint4*)&xw[0][xrow][xo + 8] = tb;
            sp  = xsrc(seqmap(1));
            r0a = __ldcg((const uint4*)(sp + xo));
            r0b = __ldcg((const uint4*)(sp + xo + 8));
            sp  = xsrc(seqmap(2));
            r1a = __ldcg((const uint4*)(sp + xo));
            r1b = __ldcg((const uint4*)(sp + xo + 8));
        }
        __syncwarp();

        #pragma unroll 1
        for (int i = 0; i < 24; i += 2) {
            // even slot: compute seq i from buf0
            compute_chunk(0, seqmap(i));
            *(uint4*)&xw[1][xrow][xo]     = r0a;     // stage seq i+1
            *(uint4*)&xw[1][xrow][xo + 8] = r0b;
            if (i + 3 < 24) {                         // prefetch seq i+3
                const __half* sp = xsrc(seqmap(i + 3));
                r0a = __ldcg((const uint4*)(sp + xo));
                r0b = __ldcg((const uint4*)(sp + xo + 8));
            }
            __syncwarp();
            // odd slot: compute seq i+1 from buf1
            compute_chunk(1, seqmap(i + 1));
            if (i + 2 < 24) {                         // stage seq i+2
                *(uint4*)&xw[0][xrow][xo]     = r1a;
                *(uint4*)&xw[0][xrow][xo + 8] = r1b;
            }
            if (i + 4 < 24) {                         // prefetch seq i+4
                if (needs_ctx && i == 4) {
                    // seq 8 is the first ctx chunk: wait for all CTAs' phase C
                    // of step t-1 before touching g_ctx.
                    const unsigned want = (unsigned)(NCTA * t);
                    while (*(volatile unsigned*)&g_cctr < want) { }
                    __threadfence();
                }
                const __half* sp = xsrc(seqmap(i + 4));
                r1a = __ldcg((const uint4*)(sp + xo));
                r1b = __ldcg((const uint4*)(sp + xo + 8));
            }
            __syncwarp();
        }
        __syncthreads();

        // K-split reduction: store frags, reduce over kq in fixed order
        #pragma unroll
        for (int nt = 0; nt < 4; ++nt) {
            #pragma unroll
            for (int i = 0; i < 4; ++i) {
                int r = gg + ((i >> 1) << 3);
                int c = nt * 8 + tg * 2 + (i & 1);
                sm.u.redA[kq][bt][r][c] = acc[nt * 4 + i];
            }
        }
        __syncthreads();
        #pragma unroll
        for (int rep = 0; rep < 4; ++rep) {
            int f = tid + rep * 256;               // 0..1023
            int bt2 = f >> 9, q = f & 511, r = q >> 5, c = q & 31;
            float v = sm.u.redA[0][bt2][r][c] + sm.u.redA[1][bt2][r][c]
                    + sm.u.redA[2][bt2][r][c] + sm.u.redA[3][bt2][r][c];
            sm.gates[bt2 * 16 + r][c] = v;
        }
        __syncthreads();

        // ---- LSTM cell (thread = (batch, unit)) ----
        {
            int bb = tid >> 3, uu = tid & 7;
            float ig = sm.gates[bb][uu]      + sm.biasv[uu];
            float fg = sm.gates[bb][8 + uu]  + sm.biasv[8 + uu];
            float gv = sm.gates[bb][16 + uu] + sm.biasv[16 + uu];
            float og = sm.gates[bb][24 + uu] + sm.biasv[24 + uu];
            float cn = sigf(fg) * sm.cst[bb][uu] + sigf(ig) * tanhf(gv);
            sm.cst[bb][uu] = cn;
            float hv = sigf(og) * tanhf(cn);
            sm.hs[bb][uu] = hv;
            g_h[p ^ 1][bb * DD + cta * 8 + uu] = __float2half(hv);
        }
        __syncthreads();

        // ---- phi partials over this CTA's 8 units (double-buffered by t&1) ----
        #pragma unroll
        for (int it = 0; it < 4; ++it) {
            int idx = tid + it * 256;
            if (idx < 960) {
                int pb = idx / 30, j = idx - pb * 30;
                float s = 0.f;
                #pragma unroll
                for (int uu = 0; uu < 8; ++uu) s += sm.hs[pb][uu] * sm.Wg[j][uu];
                g_phipart[p][cta][pb][j] = s;
            }
        }

        flagbar(cta, tid, (unsigned)(t + 1));   // phi + h visible everywhere

        // ================= Phase B : mixture head (batch b) =================
        if (tid < 240) {
            int j = tid % 30, cg = tid / 30;
            float s = 0.f;
            int c0 = cg * 16;
            #pragma unroll
            for (int c = 0; c < 16; ++c) s += __ldcg(&g_phipart[p][c0 + c][b][j]);
            sm.predbuf[cg][j] = s;
        }
        __syncthreads();
        if (tid < 30) {
            float s = sm.bgs[tid];
            #pragma unroll
            for (int cg = 0; cg < 8; ++cg) s += sm.predbuf[cg][tid];
            sm.phired[tid] = s;
        }
        __syncthreads();

        // mixture params + dynamic window, parallel over 10 lanes of warp 0
        if (wid == 0) {
            float pha = (lane < MM) ? sm.phired[20 + lane] : -1e30f;
            float mx = pha;
            #pragma unroll
            for (int off = 16; off >= 1; off >>= 1)
                mx = fmaxf(mx, __shfl_xor_sync(0xffffffffu, mx, off));
            float e = (lane < MM) ? __expf(pha - mx) : 0.f;
            float ssum = e;
            #pragma unroll
            for (int off = 16; off >= 1; off >>= 1)
                ssum += __shfl_xor_sync(0xffffffffu, ssum, off);
            float kv = 0.f, beta = 0.f;
            if (lane < MM) {
                float phb = sm.phired[10 + lane];
                kv   = sm.ksi[lane] + __expf(sm.phired[lane]);
                beta = __expf(phb);
                sm.ksi[lane]   = kv;
                sm.rbeta[lane] = __expf(-phb);
                sm.alpha[lane] = __fdividef(e, ssum);
            }
            float lof = (lane < MM) ? (kv - 14.f * beta - 1.5f) :  1e30f;
            float hif = (lane < MM) ? (kv + 14.f * beta + 0.5f) : -1e30f;
            #pragma unroll
            for (int off = 16; off >= 1; off >>= 1) {
                lof = fminf(lof, __shfl_xor_sync(0xffffffffu, lof, off));
                hif = fmaxf(hif, __shfl_xor_sync(0xffffffffu, hif, off));
            }
            if (lane == 0) {
                int lo = (int)floorf(lof); if (lo < 0) lo = 0; if (lo > SS) lo = SS;
                int hi = (int)ceilf(hif) + 1; if (hi > SS) hi = SS; if (hi < lo) hi = lo;
                sm.winlo = lo; sm.winhi = hi;
            }
        }
        __syncthreads();

        // telescoped CDF: Fbuf[idx] = F(idx-1), idx = 0..512
        #pragma unroll
        for (int rep = 0; rep < 3; ++rep) {
            int idx = tid + rep * 256;
            if (idx < 513) {
                float su = (float)(idx - 1);
                float F = 0.f;
                #pragma unroll
                for (int m = 0; m < MM; ++m)
                    F += sm.alpha[m] * sigf((su + 1.5f - sm.ksi[m]) * sm.rbeta[m]);
                sm.Fbuf[idx] = F;
            }
        }
        __syncthreads();

        // w[s] = F(s) - F(s-1); write alignment for this step
        #pragma unroll
        for (int rep = 0; rep < 2; ++rep) {
            int s = tid + rep * 256;
            float w = sm.Fbuf[s + 1] - sm.Fbuf[s];
            sm.wbuf[s] = w;
            if (dg == 0) out[ALIGN_OFF + ((size_t)b * TT + t) * SS + s] = w;
        }
        // termination (last step): 1 - F(len-1)
        if (t == TT - 1 && dg == 0 && tid == 0) {
            int sl = lens[b] - 1;
            out[TERM_OFF + b] = 1.f - sm.Fbuf[sl + 1];
        }
        __syncthreads();

        // ================= Phase C : ctx = w @ memory (windowed) =================
        {
            const int lo = sm.winlo, hi = sm.winhi;
            float accv[8];
            #pragma unroll
            for (int j = 0; j < 8; ++j) accv[j] = 0.f;
            const __half* mpb = g_mem + (size_t)b * SS * DD + dg * 256 + lane * 8;
            // warp wid covers s ≡ lo+wid (mod 8); 4-deep load batching for MLP
            for (int s0 = lo + wid; s0 < hi; s0 += 32) {
                uint4 v[4]; float wv[4];
                #pragma unroll
                for (int j = 0; j < 4; ++j) {
                    int s = s0 + 8 * j;
                    if (s < hi) {
                        v[j]  = __ldg((const uint4*)(mpb + (size_t)s * DD));
                        wv[j] = sm.wbuf[s];
                    }
                }
                #pragma unroll
                for (int j = 0; j < 4; ++j) {
                    int s = s0 + 8 * j;
                    if (s < hi) {
                        const __half2* h2 = (const __half2*)&v[j];
                        #pragma unroll
                        for (int q = 0; q < 4; ++q) {
                            float2 f = __half22float2(h2[q]);
                            accv[2 * q]     += wv[j] * f.x;
                            accv[2 * q + 1] += wv[j] * f.y;
                        }
                    }
                }
            }
            float* cr = sm.u.cred[wid];
            #pragma unroll
            for (int j = 0; j < 8; ++j) cr[lane * 8 + j] = accv[j];
        }
        __syncthreads();
        {
            int d = tid;                       // 0..255 within this CTA's d-slice
            float s0 = 0.f;
            #pragma unroll
            for (int w = 0; w < 8; ++w) s0 += sm.u.cred[w][d];
            g_ctx[b * DD + dg * 256 + d] = __float2half(s0);
            if (t == TT - 1) out[b * DD + dg * 256 + d] = s0;
        }
        __syncthreads();
        if (tid == 0) {
            __threadfence();
            atomicAdd(&g_cctr, 1u);            // phase-C completion (replaces barrier2)
        }
    }
}

extern "C" void kernel_launch(void* const* d_in, const int* in_sizes, int n_in,
                              void* d_out, int out_size) {
    const float* in_h   = (const float*)d_in[0];
    const float* mem    = (const float*)d_in[1];
    const int*   lens   = (const int*)d_in[2];
    const float* W_ih   = (const float*)d_in[3];
    const float* W_hh   = (const float*)d_in[4];
    const float* b_ih   = (const float*)d_in[5];
    const float* b_hh   = (const float*)d_in[6];
    const float* W_g    = (const float*)d_in[7];
    const float* b_g    = (const float*)d_in[8];
    float* out = (float*)d_out;

    cudaFuncSetAttribute(tts_main, cudaFuncAttributeMaxDynamicSharedMemorySize,
                         (int)sizeof(Smem));

    tts_prep<<<1024, 256>>>(in_h, mem);
    tts_main<<<NCTA, NTHR, sizeof(Smem)>>>(W_ih, W_hh, b_ih, b_hh, W_g, b_g, lens, out);
}

// round 8
// speedup vs baseline: 1.2313x; 1.0331x over previous
#include <cuda_runtime.h>
#include <cuda_fp16.h>
#include <math.h>
#include <stdint.h>

#define BB   32
#define TT   512
#define SS   512
#define DD   1024
#define MM   10
#define K3   3072
#define KP   3080      // padded K stride (halves) for Ws: conflict-free B-frag loads
#define NCTA 128
#define NTHR 256

// ---------------- static device scratch (allocations are forbidden) ----------------
__device__ __half  g_in[BB * TT * DD];          // fp16 copy of input_h_c
__device__ __half  g_mem[BB * SS * DD];         // fp16 copy of memory
__device__ __half  g_ctx[BB * DD];              // ctx_t (fp16), produced by phase C
__device__ __half  g_h[2][BB * DD];             // double-buffered h (fp16)
__device__ float   g_phipart[2][NCTA][BB][32];  // per-CTA phi partials, dbl-buffered
__device__ unsigned g_arrive[NCTA];             // flag barrier: per-CTA arrival
__device__ unsigned g_release;                  // flag barrier: release word
__device__ unsigned g_cctr;                     // phase-C completion counter (monotonic)

// ---------------- dynamic shared memory layout ----------------
struct Smem {
    __half Ws[32][KP];                 // persistent weight slice     197120 B
    union {
        __half xsw[8][2][16][40];      // per-warp x staging           20480 B
        float  redA[4][2][16][33];     // K-split reduction            16896 B
        float  cred[8][256];           // phase-C cross-warp reduce     8192 B
    } u;
    float gates[32][32];               // reduced gate tile             4096 B
    float cst[32][8];                  // persistent cell state         1024 B
    float hs[32][8];                   // fp32 h slice                  1024 B
    float Wg[32][8];                   // W_g slice (30 used)           1024 B
    float biasv[32];                   // b_ih + b_hh per local col      128 B
    float bgs[32];                     // b_g (30 used)                  128 B
    float predbuf[8][32];              // phi reduce stage               1024 B
    float phired[32];                  // reduced phi (30 used)           128 B
    float wbuf[SS];                    // attention weights              2048 B
    float Fbuf[520];                   // windowed CDF values           2080 B
    float ksi[16];                     // persistent ksi                   64 B
    float rbeta[16];                   // 1/beta                           64 B
    float alpha[16];                   // softmax alpha                    64 B
    int   winlo, winhi;                // phase-C / CDF window             8 B
};

// ---------------- flag + release grid barrier (R4/R7-proven) ----------------
__device__ __forceinline__ void flagbar(int cta, int tid, unsigned want) {
    __syncthreads();
    if (cta == 0) {
        if (tid == 0) {
            __threadfence();
            *(volatile unsigned*)&g_arrive[0] = want;
        }
        if (tid < NCTA) {
            while (*(volatile unsigned*)&g_arrive[tid] < want) { }
        }
        __syncthreads();
        if (tid == 0) {
            __threadfence();
            *(volatile unsigned*)&g_release = want;
        }
    } else {
        if (tid == 0) {
            __threadfence();
            *(volatile unsigned*)&g_arrive[cta] = want;
            while (*(volatile unsigned*)&g_release < want) { }
            __threadfence();
        }
    }
    __syncthreads();
}

// ---------------- prep: fp32 -> fp16 conversions + state reset ----------------
__global__ void tts_prep(const float* __restrict__ in, const float* __restrict__ mem) {
    const int tid = blockIdx.x * blockDim.x + threadIdx.x;
    const int np  = gridDim.x * blockDim.x;
    const int N1  = BB * TT * DD;
    for (int i = tid; i < N1; i += np) g_in[i]  = __float2half(in[i]);
    for (int i = tid; i < N1; i += np) g_mem[i] = __float2half(mem[i]);
    for (int i = tid; i < BB * DD; i += np) {
        g_ctx[i]  = __float2half(0.f);
        g_h[0][i] = __float2half(0.f);
        g_h[1][i] = __float2half(0.f);
    }
    if (tid < NCTA) g_arrive[tid] = 0u;
    if (tid == 0) { g_release = 0u; g_cctr = 0u; }
}

#define MMA_16816(ac, A0, A1, A2, A3, B0, B1)                               \
    asm volatile(                                                           \
        "mma.sync.aligned.m16n8k16.row.col.f32.f16.f16.f32 "                \
        "{%0,%1,%2,%3}, {%4,%5,%6,%7}, {%8,%9}, {%0,%1,%2,%3};"             \
        : "+f"((ac)[0]), "+f"((ac)[1]), "+f"((ac)[2]), "+f"((ac)[3])        \
        : "r"(A0), "r"(A1), "r"(A2), "r"(A3), "r"(B0), "r"(B1))

__device__ __forceinline__ float sigf(float x) {          // accurate (2 MUFU)
    return __fdividef(1.f, 1.f + __expf(-x));
}
__device__ __forceinline__ float sig_tanh(float z) {      // fast (1 MUFU)
    float t;
    asm("tanh.approx.f32 %0, %1;" : "=f"(t) : "f"(z * 0.5f));
    return fmaf(t, 0.5f, 0.5f);
}

// ---------------- main persistent kernel ----------------
__global__ void __launch_bounds__(NTHR, 1) tts_main(
    const float* __restrict__ W_ih, const float* __restrict__ W_hh,
    const float* __restrict__ b_ih, const float* __restrict__ b_hh,
    const float* __restrict__ W_g,  const float* __restrict__ b_g,
    const int*   __restrict__ lens, float* __restrict__ out)
{
    extern __shared__ char smraw[];
    Smem& sm = *reinterpret_cast<Smem*>(smraw);
    const int tid  = threadIdx.x;
    const int cta  = blockIdx.x;
    const int wid  = tid >> 5;
    const int lane = tid & 31;

    const size_t ALIGN_OFF = (size_t)BB * DD;                      // 32768
    const size_t TERM_OFF  = ALIGN_OFF + (size_t)BB * TT * SS;     // 8421376

    // ---- one-time init ----
    for (int i = tid; i < 32 * K3; i += NTHR) {
        int c = i / K3, k = i - c * K3;
        int gcol = (c >> 3) * DD + cta * 8 + (c & 7);
        float wv = (k < 2048) ? W_ih[(size_t)gcol * 2048 + k]
                              : W_hh[(size_t)gcol * DD + (k - 2048)];
        sm.Ws[c][k] = __float2half(wv);
    }
    if (tid < 240) {
        int j = tid >> 3, uu = tid & 7;
        sm.Wg[j][uu] = W_g[(size_t)j * DD + cta * 8 + uu];
    }
    if (tid < 32) {
        int gcol = (tid >> 3) * DD + cta * 8 + (tid & 7);
        sm.biasv[tid] = b_ih[gcol] + b_hh[gcol];
    }
    if (tid < 30) sm.bgs[tid] = b_g[tid];
    { int b2 = tid >> 3, uu = tid & 7; sm.cst[b2][uu] = 0.f; }
    if (tid < 16) { sm.ksi[tid] = 0.f; sm.rbeta[tid] = 0.f; sm.alpha[tid] = 0.f; }
    __syncthreads();

    // warp roles for the gate GEMM
    const int bt = wid & 1;          // batch-half (rows bt*16 .. +16)
    const int kq = wid >> 1;         // K-quarter  (k in [kq*768, +768))
    const int gg = lane >> 2;        // mma group id (0..7)
    const int tg = lane & 3;         // thread-in-group (0..3)
    __half (&xw)[2][16][40] = sm.u.xsw[wid];
    const int xrow = lane >> 1;              // 0..15
    const int xb   = bt * 16 + xrow;         // global batch
    const int xo   = (lane & 1) * 16;        // half-offset within 32-half chunk
    const bool needs_ctx = (kq == 1 || kq == 2);

    // phase B/C roles
    const int b  = cta & 31;     // batch
    const int dg = cta >> 5;     // d-slice (0..3) of 256

    for (int t = 0; t < TT; ++t) {
        const int p = t & 1;

        // ================= Phase A : gate GEMM =================
        float acc[16];
        #pragma unroll
        for (int i = 0; i < 16; ++i) acc[i] = 0.f;

        auto seqmap = [&](int i) -> int {
            return (kq == 2) ? ((i < 8) ? i + 16 : i - 8) : i;
        };
        auto xsrc = [&](int kc) -> const __half* {
            int kk = kq * 768 + kc * 32;
            if (kk < 1024) return g_in  + ((size_t)xb * TT + t) * DD + kk;
            if (kk < 2048) return g_ctx + xb * DD + (kk - 1024);
            return g_h[p] + xb * DD + (kk - 2048);
        };
        auto compute_chunk = [&](int buf, int kc) {
            const int k0 = kq * 768 + kc * 32;
            #pragma unroll
            for (int kt = 0; kt < 2; ++kt) {
                const int kb = kt * 16;
                unsigned a0 = *(const unsigned*)&xw[buf][gg    ][kb + 2 * tg];
                unsigned a1 = *(const unsigned*)&xw[buf][gg + 8][kb + 2 * tg];
                unsigned a2 = *(const unsigned*)&xw[buf][gg    ][kb + 2 * tg + 8];
                unsigned a3 = *(const unsigned*)&xw[buf][gg + 8][kb + 2 * tg + 8];
                const int kg = k0 + kb;
                #pragma unroll
                for (int nt = 0; nt < 4; ++nt) {
                    unsigned b0 = *(const unsigned*)&sm.Ws[nt * 8 + gg][kg + 2 * tg];
                    unsigned b1 = *(const unsigned*)&sm.Ws[nt * 8 + gg][kg + 2 * tg + 8];
                    MMA_16816(acc + nt * 4, a0, a1, a2, a3, b0, b1);
                }
            }
        };

        uint4 r0a, r0b, r1a, r1b;
        {   // prologue: seq0 -> buf0, seq1 -> r0, seq2 -> r1 (all non-ctx)
            const __half* sp = xsrc(seqmap(0));
            uint4 ta = __ldcg((const uint4*)(sp + xo));
            uint4 tb = __ldcg((const uint4*)(sp + xo + 8));
            *(uint4*)&xw[0][xrow][xo]     = ta;
            *(uint4*)&xw[0][xrow][xo + 8] = tb;
            sp  = xsrc(seqmap(1));
            r0a = __ldcg((const uint4*)(sp + xo));
            r0b = __ldcg((const uint4*)(sp + xo + 8));
            sp  = xsrc(seqmap(2));
            r1a = __ldcg((const uint4*)(sp + xo));
            r1b = __ldcg((const uint4*)(sp + xo + 8));
        }
        __syncwarp();

        #pragma unroll 1
        for (int i = 0; i < 24; i += 2) {
            compute_chunk(0, seqmap(i));
            *(uint4*)&xw[1][xrow][xo]     = r0a;
            *(uint4*)&xw[1][xrow][xo + 8] = r0b;
            if (i + 3 < 24) {
                const __half* sp = xsrc(seqmap(i + 3));
                r0a = __ldcg((const uint4*)(sp + xo));
                r0b = __ldcg((const uint4*)(sp + xo + 8));
            }
            __syncwarp();
            compute_chunk(1, seqmap(i + 1));
            if (i + 2 < 24) {
                *(uint4*)&xw[0][xrow][xo]     = r1a;
                *(uint4*)&xw[0][xrow][xo + 8] = r1b;
            }
            if (i + 4 < 24) {
                if (needs_ctx && i == 4) {
                    const unsigned want = (unsigned)(NCTA * t);
                    while (*(volatile unsigned*)&g_cctr < want) { }
                    __threadfence();
                }
                const __half* sp = xsrc(seqmap(i + 4));
                r1a = __ldcg((const uint4*)(sp + xo));
                r1b = __ldcg((const uint4*)(sp + xo + 8));
            }
            __syncwarp();
        }
        __syncthreads();

        // K-split reduction: store frags, reduce over kq in fixed order
        #pragma unroll
        for (int nt = 0; nt < 4; ++nt) {
            #pragma unroll
            for (int i = 0; i < 4; ++i) {
                int r = gg + ((i >> 1) << 3);
                int c = nt * 8 + tg * 2 + (i & 1);
                sm.u.redA[kq][bt][r][c] = acc[nt * 4 + i];
            }
        }
        __syncthreads();
        #pragma unroll
        for (int rep = 0; rep < 4; ++rep) {
            int f = tid + rep * 256;               // 0..1023
            int bt2 = f >> 9, q = f & 511, r = q >> 5, c = q & 31;
            float v = sm.u.redA[0][bt2][r][c] + sm.u.redA[1][bt2][r][c]
                    + sm.u.redA[2][bt2][r][c] + sm.u.redA[3][bt2][r][c];
            sm.gates[bt2 * 16 + r][c] = v;
        }
        __syncthreads();

        // ---- LSTM cell (thread = (batch, unit)) ----
        {
            int bb = tid >> 3, uu = tid & 7;
            float ig = sm.gates[bb][uu]      + sm.biasv[uu];
            float fg = sm.gates[bb][8 + uu]  + sm.biasv[8 + uu];
            float gv = sm.gates[bb][16 + uu] + sm.biasv[16 + uu];
            float og = sm.gates[bb][24 + uu] + sm.biasv[24 + uu];
            float cn = sigf(fg) * sm.cst[bb][uu] + sigf(ig) * tanhf(gv);
            sm.cst[bb][uu] = cn;
            float hv = sigf(og) * tanhf(cn);
            sm.hs[bb][uu] = hv;
            g_h[p ^ 1][bb * DD + cta * 8 + uu] = __float2half(hv);
        }
        __syncthreads();

        // ---- phi partials over this CTA's 8 units (double-buffered by t&1) ----
        #pragma unroll
        for (int it = 0; it < 4; ++it) {
            int idx = tid + it * 256;
            if (idx < 960) {
                int pb = idx / 30, j = idx - pb * 30;
                float s = 0.f;
                #pragma unroll
                for (int uu = 0; uu < 8; ++uu) s += sm.hs[pb][uu] * sm.Wg[j][uu];
                g_phipart[p][cta][pb][j] = s;
            }
        }

        flagbar(cta, tid, (unsigned)(t + 1));   // phi + h visible everywhere

        // ================= Phase B : mixture head (batch b) =================
        if (tid < 240) {
            int j = tid % 30, cg = tid / 30;
            float s = 0.f;
            int c0 = cg * 16;
            #pragma unroll
            for (int c = 0; c < 16; ++c) s += __ldcg(&g_phipart[p][c0 + c][b][j]);
            sm.predbuf[cg][j] = s;
        }
        __syncthreads();
        if (tid < 30) {
            float s = sm.bgs[tid];
            #pragma unroll
            for (int cg = 0; cg < 8; ++cg) s += sm.predbuf[cg][tid];
            sm.phired[tid] = s;
        }
        __syncthreads();

        // mixture params + dynamic window, parallel over 10 lanes of warp 0
        if (wid == 0) {
            float pha = (lane < MM) ? sm.phired[20 + lane] : -1e30f;
            float mx = pha;
            #pragma unroll
            for (int off = 16; off >= 1; off >>= 1)
                mx = fmaxf(mx, __shfl_xor_sync(0xffffffffu, mx, off));
            float e = (lane < MM) ? __expf(pha - mx) : 0.f;
            float ssum = e;
            #pragma unroll
            for (int off = 16; off >= 1; off >>= 1)
                ssum += __shfl_xor_sync(0xffffffffu, ssum, off);
            float kv = 0.f, beta = 0.f;
            if (lane < MM) {
                float phb = sm.phired[10 + lane];
                kv   = sm.ksi[lane] + __expf(sm.phired[lane]);
                beta = __expf(phb);
                sm.ksi[lane]   = kv;
                sm.rbeta[lane] = __expf(-phb);
                sm.alpha[lane] = __fdividef(e, ssum);
            }
            float lof = (lane < MM) ? (kv - 14.f * beta - 1.5f) :  1e30f;
            float hif = (lane < MM) ? (kv + 14.f * beta + 0.5f) : -1e30f;
            #pragma unroll
            for (int off = 16; off >= 1; off >>= 1) {
                lof = fminf(lof, __shfl_xor_sync(0xffffffffu, lof, off));
                hif = fmaxf(hif, __shfl_xor_sync(0xffffffffu, hif, off));
            }
            if (lane == 0) {
                int lo = (int)floorf(lof); if (lo < 0) lo = 0; if (lo > SS) lo = SS;
                int hi = (int)ceilf(hif) + 1; if (hi > SS) hi = SS; if (hi < lo) hi = lo;
                sm.winlo = lo; sm.winhi = hi;
            }
        }
        __syncthreads();

        // ---- windowed telescoped CDF ----
        // Need F(s') for s' in [lo-1, hi-1] to form w[s]=F(s)-F(s-1), s in [lo,hi).
        // Fbuf[j] = F(lo-1+j), j = 0..n-1, n = hi-lo+1. Outside the window
        // |w| <= 10*e^-14 ~ 8e-7 -> written as 0.
        const int wlo = sm.winlo, whi = sm.winhi;
        const int nF  = whi - wlo + 1;
        #pragma unroll 1
        for (int j = tid; j < nF; j += NTHR) {
            float su = (float)(wlo - 1 + j);
            float F = 0.f;
            #pragma unroll
            for (int m = 0; m < MM; ++m)
                F += sm.alpha[m] * sig_tanh((su + 1.5f - sm.ksi[m]) * sm.rbeta[m]);
            sm.Fbuf[j] = F;
        }
        __syncthreads();

        // w[s] = F(s) - F(s-1) inside window, else 0; write alignment
        #pragma unroll
        for (int rep = 0; rep < 2; ++rep) {
            int s = tid + rep * 256;
            float w = 0.f;
            if (s >= wlo && s < whi)
                w = sm.Fbuf[s - wlo + 1] - sm.Fbuf[s - wlo];
            sm.wbuf[s] = w;
            if (dg == 0) out[ALIGN_OFF + ((size_t)b * TT + t) * SS + s] = w;
        }
        // termination (last step): exact exp-based formula on its one element
        if (t == TT - 1 && dg == 0 && tid == 0) {
            float su = (float)(lens[b] - 1);
            float t1 = 0.f;
            #pragma unroll
            for (int m = 0; m < MM; ++m)
                t1 += sm.alpha[m] * sigf((su + 1.5f - sm.ksi[m]) * sm.rbeta[m]);
            out[TERM_OFF + b] = 1.f - t1;
        }
        __syncthreads();

        // ================= Phase C : ctx = w @ memory (windowed) =================
        {
            const int lo = wlo, hi = whi;
            float accv[8];
            #pragma unroll
            for (int j = 0; j < 8; ++j) accv[j] = 0.f;
            const __half* mpb = g_mem + (size_t)b * SS * DD + dg * 256 + lane * 8;
            for (int s0 = lo + wid; s0 < hi; s0 += 32) {
                uint4 v[4]; float wv[4];
                #pragma unroll
                for (int j = 0; j < 4; ++j) {
                    int s = s0 + 8 * j;
                    if (s < hi) {
                        v[j]  = __ldg((const uint4*)(mpb + (size_t)s * DD));
                        wv[j] = sm.wbuf[s];
                    }
                }
                #pragma unroll
                for (int j = 0; j < 4; ++j) {
                    int s = s0 + 8 * j;
                    if (s < hi) {
                        const __half2* h2 = (const __half2*)&v[j];
                        #pragma unroll
                        for (int q = 0; q < 4; ++q) {
                            float2 f = __half22float2(h2[q]);
                            accv[2 * q]     += wv[j] * f.x;
                            accv[2 * q + 1] += wv[j] * f.y;
                        }
                    }
                }
            }
            float* cr = sm.u.cred[wid];
            #pragma unroll
            for (int j = 0; j < 8; ++j) cr[lane * 8 + j] = accv[j];
        }
        __syncthreads();
        {
            int d = tid;                       // 0..255 within this CTA's d-slice
            float s0 = 0.f;
            #pragma unroll
            for (int w = 0; w < 8; ++w) s0 += sm.u.cred[w][d];
            g_ctx[b * DD + dg * 256 + d] = __float2half(s0);
            if (t == TT - 1) out[b * DD + dg * 256 + d] = s0;
        }
        __syncthreads();
        if (tid == 0) {
            __threadfence();
            atomicAdd(&g_cctr, 1u);            // phase-C completion (replaces barrier2)
        }
    }
}

extern "C" void kernel_launch(void* const* d_in, const int* in_sizes, int n_in,
                              void* d_out, int out_size) {
    const float* in_h   = (const float*)d_in[0];
    const float* mem    = (const float*)d_in[1];
    const int*   lens   = (const int*)d_in[2];
    const float* W_ih   = (const float*)d_in[3];
    const float* W_hh   = (const float*)d_in[4];
    const float* b_ih   = (const float*)d_in[5];
    const float* b_hh   = (const float*)d_in[6];
    const float* W_g    = (const float*)d_in[7];
    const float* b_g    = (const float*)d_in[8];
    float* out = (float*)d_out;

    cudaFuncSetAttribute(tts_main, cudaFuncAttributeMaxDynamicSharedMemorySize,
                         (int)sizeof(Smem));

    tts_prep<<<1024, 256>>>(in_h, mem);
    tts_main<<<NCTA, NTHR, sizeof(Smem)>>>(W_ih, W_hh, b_ih, b_hh, W_g, b_g, lens, out);
}

// round 10
// speedup vs baseline: 1.2434x; 1.0098x over previous
#include <cuda_runtime.h>
#include <cuda_fp16.h>
#include <math.h>
#include <stdint.h>

#define BB   32
#define TT   512
#define SS   512
#define DD   1024
#define MM   10
#define K3   3072
#define KP   3080      // padded K stride (halves) for Ws: conflict-free B-frag loads
#define NCTA 128
#define NTHR 512

// ---------------- static device scratch (allocations are forbidden) ----------------
__device__ __half  g_in[BB * TT * DD];          // fp16 copy of input_h_c
__device__ __half  g_mem[BB * SS * DD];         // fp16 copy of memory
__device__ __half  g_ctx[BB * DD];              // ctx_t (fp16), produced by phase C
__device__ __half  g_h[2][BB * DD];             // double-buffered h (fp16)
__device__ float   g_phipart[2][NCTA][BB][32];  // per-CTA phi partials, dbl-buffered
__device__ unsigned g_arrive[NCTA];             // flag barrier: per-CTA arrival
__device__ unsigned g_release;                  // flag barrier: release word
__device__ unsigned g_cctr;                     // phase-C completion counter (monotonic)

// ---------------- dynamic shared memory layout ----------------
struct Smem {
    __half Ws[32][KP];                 // persistent weight slice     197120 B
    union {
        __half xsw[16][2][16][24];     // per-warp x staging (k16)    24576 B
        float  redA[4][2][16][33];     // K-split reduction (2-pass)  16896 B
        float  cred[16][256];          // phase-C cross-warp reduce   16384 B
        struct {                       // phase-B scratch
            float Fbuf[520];           // windowed CDF
            float predbuf[8][32];      // phi reduce stage
            float phired[32];          // reduced phi
        } pb;
    } u;
    float gates[32][32];               // reduced gate tile             4096 B
    float cst[32][8];                  // persistent cell state         1024 B
    float hs[32][8];                   // fp32 h slice                  1024 B
    float Wg[32][8];                   // W_g slice (30 used)           1024 B
    float biasv[32];                   // b_ih + b_hh per local col      128 B
    float bgs[32];                     // b_g (30 used)                  128 B
    float wbuf[SS];                    // attention weights              2048 B
    float ksi[16];                     // persistent ksi                   64 B
    float rbeta[16];                   // 1/beta                           64 B
    float alpha[16];                   // softmax alpha                    64 B
    int   winlo, winhi;                // phase-C / CDF window             8 B
};

// ---------------- flag + release grid barrier (R4/R7-proven) ----------------
__device__ __forceinline__ void flagbar(int cta, int tid, unsigned want) {
    __syncthreads();
    if (cta == 0) {
        if (tid == 0) {
            __threadfence();
            *(volatile unsigned*)&g_arrive[0] = want;
        }
        if (tid < NCTA) {
            while (*(volatile unsigned*)&g_arrive[tid] < want) { }
        }
        __syncthreads();
        if (tid == 0) {
            __threadfence();
            *(volatile unsigned*)&g_release = want;
        }
    } else {
        if (tid == 0) {
            __threadfence();
            *(volatile unsigned*)&g_arrive[cta] = want;
            while (*(volatile unsigned*)&g_release < want) { }
            __threadfence();
        }
    }
    __syncthreads();
}

// ---------------- prep: fp32 -> fp16 conversions + state reset ----------------
__global__ void tts_prep(const float* __restrict__ in, const float* __restrict__ mem) {
    const int tid = blockIdx.x * blockDim.x + threadIdx.x;
    const int np  = gridDim.x * blockDim.x;
    const int N1  = BB * TT * DD;
    for (int i = tid; i < N1; i += np) g_in[i]  = __float2half(in[i]);
    for (int i = tid; i < N1; i += np) g_mem[i] = __float2half(mem[i]);
    for (int i = tid; i < BB * DD; i += np) {
        g_ctx[i]  = __float2half(0.f);
        g_h[0][i] = __float2half(0.f);
        g_h[1][i] = __float2half(0.f);
    }
    if (tid < NCTA) g_arrive[tid] = 0u;
    if (tid == 0) { g_release = 0u; g_cctr = 0u; }
}

#define MMA_16816(ac, A0, A1, A2, A3, B0, B1)                               \
    asm volatile(                                                           \
        "mma.sync.aligned.m16n8k16.row.col.f32.f16.f16.f32 "                \
        "{%0,%1,%2,%3}, {%4,%5,%6,%7}, {%8,%9}, {%0,%1,%2,%3};"             \
        : "+f"((ac)[0]), "+f"((ac)[1]), "+f"((ac)[2]), "+f"((ac)[3])        \
        : "r"(A0), "r"(A1), "r"(A2), "r"(A3), "r"(B0), "r"(B1))

__device__ __forceinline__ float sigf(float x) {          // accurate (2 MUFU)
    return __fdividef(1.f, 1.f + __expf(-x));
}
__device__ __forceinline__ float sig_tanh(float z) {      // fast (1 MUFU)
    float t;
    asm("tanh.approx.f32 %0, %1;" : "=f"(t) : "f"(z * 0.5f));
    return fmaf(t, 0.5f, 0.5f);
}

// seq index (0..23) -> perm value: 8 x-chunks, 8 h-chunks, then 8 ctx-chunks
__device__ __forceinline__ int permv(int i) {
    return (i < 8) ? i : ((i < 16) ? i + 8 : i - 8);
}

// ---------------- main persistent kernel ----------------
__global__ void __launch_bounds__(NTHR, 1) tts_main(
    const float* __restrict__ W_ih, const float* __restrict__ W_hh,
    const float* __restrict__ b_ih, const float* __restrict__ b_hh,
    const float* __restrict__ W_g,  const float* __restrict__ b_g,
    const int*   __restrict__ lens, float* __restrict__ out)
{
    extern __shared__ char smraw[];
    Smem& sm = *reinterpret_cast<Smem*>(smraw);
    const int tid  = threadIdx.x;
    const int cta  = blockIdx.x;
    const int wid  = tid >> 5;
    const int lane = tid & 31;

    const size_t ALIGN_OFF = (size_t)BB * DD;                      // 32768
    const size_t TERM_OFF  = ALIGN_OFF + (size_t)BB * TT * SS;     // 8421376

    // ---- one-time init ----
    for (int i = tid; i < 32 * K3; i += NTHR) {
        int c = i / K3, k = i - c * K3;
        int gcol = (c >> 3) * DD + cta * 8 + (c & 7);
        float wv = (k < 2048) ? W_ih[(size_t)gcol * 2048 + k]
                              : W_hh[(size_t)gcol * DD + (k - 2048)];
        sm.Ws[c][k] = __float2half(wv);
    }
    if (tid < 240) {
        int j = tid >> 3, uu = tid & 7;
        sm.Wg[j][uu] = W_g[(size_t)j * DD + cta * 8 + uu];
    }
    if (tid < 32) {
        int gcol = (tid >> 3) * DD + cta * 8 + (tid & 7);
        sm.biasv[tid] = b_ih[gcol] + b_hh[gcol];
    }
    if (tid < 30) sm.bgs[tid] = b_g[tid];
    if (tid < 256) { int b2 = tid >> 3, uu = tid & 7; sm.cst[b2][uu] = 0.f; }
    if (tid < 16) { sm.ksi[tid] = 0.f; sm.rbeta[tid] = 0.f; sm.alpha[tid] = 0.f; }
    __syncthreads();

    // warp roles for the gate GEMM: 16 warps = (bt M-half) x (kw 8-way strided K)
    const int bt = wid & 1;          // batch-half (rows bt*16 .. +16)
    const int kw = wid >> 1;         // K stride class: chunks kw + 8*j
    const int gg = lane >> 2;        // mma group id (0..7)
    const int tg = lane & 3;         // thread-in-group (0..3)
    __half (&xw)[2][16][24] = sm.u.xsw[wid];
    const int xrow = lane >> 1;              // 0..15
    const int xb   = bt * 16 + xrow;         // global batch
    const int xo   = (lane & 1) * 8;         // half-offset within 16-half chunk

    // phase B/C roles
    const int b  = cta & 31;     // batch
    const int dg = cta >> 5;     // d-slice (0..3) of 256

    for (int t = 0; t < TT; ++t) {
        const int p = t & 1;

        // ================= Phase A : gate GEMM =================
        float acc[16];
        #pragma unroll
        for (int i = 0; i < 16; ++i) acc[i] = 0.f;

        // seq i -> global k = 16*(kw + 8*permv(i)); x: pv<8, h: pv>=16, ctx: 8..15
        auto xsrc = [&](int i) -> const __half* {
            int pv = permv(i);
            int kk = 16 * kw + 128 * pv;
            if (pv < 8)  return g_in  + ((size_t)xb * TT + t) * DD + kk;
            if (pv >= 16) return g_h[p] + xb * DD + (kk - 2048);
            return g_ctx + xb * DD + (kk - 1024);
        };
        auto kglob = [&](int i) -> int { return 16 * kw + 128 * permv(i); };

        auto compute_chunk = [&](int buf, int i) {
            unsigned a0 = *(const unsigned*)&xw[buf][gg    ][2 * tg];
            unsigned a1 = *(const unsigned*)&xw[buf][gg + 8][2 * tg];
            unsigned a2 = *(const unsigned*)&xw[buf][gg    ][2 * tg + 8];
            unsigned a3 = *(const unsigned*)&xw[buf][gg + 8][2 * tg + 8];
            const int kg = kglob(i);
            #pragma unroll
            for (int nt = 0; nt < 4; ++nt) {
                unsigned b0 = *(const unsigned*)&sm.Ws[nt * 8 + gg][kg + 2 * tg];
                unsigned b1 = *(const unsigned*)&sm.Ws[nt * 8 + gg][kg + 2 * tg + 8];
                MMA_16816(acc + nt * 4, a0, a1, a2, a3, b0, b1);
            }
        };

        uint4 r0, r1;
        {   // prologue: seq0 -> buf0, seq1 -> r0, seq2 -> r1 (all x-chunks)
            uint4 ta = __ldcg((const uint4*)(xsrc(0) + xo));
            *(uint4*)&xw[0][xrow][xo] = ta;
            r0 = __ldcg((const uint4*)(xsrc(1) + xo));
            r1 = __ldcg((const uint4*)(xsrc(2) + xo));
        }
        __syncwarp();

        #pragma unroll 1
        for (int i = 0; i < 24; i += 2) {
            // even slot: compute seq i from buf0
            compute_chunk(0, i);
            *(uint4*)&xw[1][xrow][xo] = r0;          // stage seq i+1
            if (i + 3 < 24)                          // prefetch seq i+3
                r0 = __ldcg((const uint4*)(xsrc(i + 3) + xo));
            __syncwarp();
            // odd slot: compute seq i+1 from buf1
            compute_chunk(1, i + 1);
            if (i + 2 < 24)
                *(uint4*)&xw[0][xrow][xo] = r1;      // stage seq i+2
            if (i + 4 < 24) {
                if (i == 12) {
                    // seq 16 is the first ctx chunk: wait for all CTAs' phase C
                    // of step t-1 before touching g_ctx.
                    const unsigned want = (unsigned)(NCTA * t);
                    while (*(volatile unsigned*)&g_cctr < want) { }
                    __threadfence();
                }
                r1 = __ldcg((const uint4*)(xsrc(i + 4) + xo));
            }
            __syncwarp();
        }
        __syncthreads();

        // K-split reduction: two passes of 4 splits each (fp32, deterministic)
        #pragma unroll
        for (int pass = 0; pass < 2; ++pass) {
            if ((kw >> 2) == pass) {
                int ks = kw & 3;
                #pragma unroll
                for (int nt = 0; nt < 4; ++nt) {
                    #pragma unroll
                    for (int i = 0; i < 4; ++i) {
                        int r = gg + ((i >> 1) << 3);
                        int c = nt * 8 + tg * 2 + (i & 1);
                        sm.u.redA[ks][bt][r][c] = acc[nt * 4 + i];
                    }
                }
            }
            __syncthreads();
            #pragma unroll
            for (int rep = 0; rep < 2; ++rep) {
                int f = tid + rep * NTHR;              // 0..1023
                int bt2 = f >> 9, q = f & 511, r = q >> 5, c = q & 31;
                float v = sm.u.redA[0][bt2][r][c] + sm.u.redA[1][bt2][r][c]
                        + sm.u.redA[2][bt2][r][c] + sm.u.redA[3][bt2][r][c];
                if (pass == 0) sm.gates[bt2 * 16 + r][c] = v;
                else           sm.gates[bt2 * 16 + r][c] += v;
            }
            __syncthreads();
        }

        // ---- LSTM cell (thread = (batch, unit)) ----
        if (tid < 256) {
            int bb = tid >> 3, uu = tid & 7;
            float ig = sm.gates[bb][uu]      + sm.biasv[uu];
            float fg = sm.gates[bb][8 + uu]  + sm.biasv[8 + uu];
            float gv = sm.gates[bb][16 + uu] + sm.biasv[16 + uu];
            float og = sm.gates[bb][24 + uu] + sm.biasv[24 + uu];
            float cn = sigf(fg) * sm.cst[bb][uu] + sigf(ig) * tanhf(gv);
            sm.cst[bb][uu] = cn;
            float hv = sigf(og) * tanhf(cn);
            sm.hs[bb][uu] = hv;
            g_h[p ^ 1][bb * DD + cta * 8 + uu] = __float2half(hv);
        }
        __syncthreads();

        // ---- phi partials over this CTA's 8 units (double-buffered by t&1) ----
        #pragma unroll
        for (int it = 0; it < 2; ++it) {
            int idx = tid + it * NTHR;
            if (idx < 960) {
                int pb = idx / 30, j = idx - pb * 30;
                float s = 0.f;
                #pragma unroll
                for (int uu = 0; uu < 8; ++uu) s += sm.hs[pb][uu] * sm.Wg[j][uu];
                g_phipart[p][cta][pb][j] = s;
            }
        }

        flagbar(cta, tid, (unsigned)(t + 1));   // phi + h visible everywhere

        // ================= Phase B : mixture head (batch b) =================
        if (tid < 240) {
            int j = tid % 30, cg = tid / 30;
            float s = 0.f;
            int c0 = cg * 16;
            #pragma unroll
            for (int c = 0; c < 16; ++c) s += __ldcg(&g_phipart[p][c0 + c][b][j]);
            sm.u.pb.predbuf[cg][j] = s;
        }
        __syncthreads();
        if (tid < 30) {
            float s = sm.bgs[tid];
            #pragma unroll
            for (int cg = 0; cg < 8; ++cg) s += sm.u.pb.predbuf[cg][tid];
            sm.u.pb.phired[tid] = s;
        }
        __syncthreads();

        // mixture params + dynamic window, parallel over 10 lanes of warp 0
        if (wid == 0) {
            float pha = (lane < MM) ? sm.u.pb.phired[20 + lane] : -1e30f;
            float mx = pha;
            #pragma unroll
            for (int off = 16; off >= 1; off >>= 1)
                mx = fmaxf(mx, __shfl_xor_sync(0xffffffffu, mx, off));
            float e = (lane < MM) ? __expf(pha - mx) : 0.f;
            float ssum = e;
            #pragma unroll
            for (int off = 16; off >= 1; off >>= 1)
                ssum += __shfl_xor_sync(0xffffffffu, ssum, off);
            float kv = 0.f, beta = 0.f;
            if (lane < MM) {
                float phb = sm.u.pb.phired[10 + lane];
                kv   = sm.ksi[lane] + __expf(sm.u.pb.phired[lane]);
                beta = __expf(phb);
                sm.ksi[lane]   = kv;
                sm.rbeta[lane] = __expf(-phb);
                sm.alpha[lane] = __fdividef(e, ssum);
            }
            float lof = (lane < MM) ? (kv - 14.f * beta - 1.5f) :  1e30f;
            float hif = (lane < MM) ? (kv + 14.f * beta + 0.5f) : -1e30f;
            #pragma unroll
            for (int off = 16; off >= 1; off >>= 1) {
                lof = fminf(lof, __shfl_xor_sync(0xffffffffu, lof, off));
                hif = fmaxf(hif, __shfl_xor_sync(0xffffffffu, hif, off));
            }
            if (lane == 0) {
                int lo = (int)floorf(lof); if (lo < 0) lo = 0; if (lo > SS) lo = SS;
                int hi = (int)ceilf(hif) + 1; if (hi > SS) hi = SS; if (hi < lo) hi = lo;
                sm.winlo = lo; sm.winhi = hi;
            }
        }
        __syncthreads();

        // ---- windowed telescoped CDF: Fbuf[j] = F(lo-1+j), j=0..n-1 ----
        const int wlo = sm.winlo, whi = sm.winhi;
        const int nF  = whi - wlo + 1;
        #pragma unroll 1
        for (int j = tid; j < nF; j += NTHR) {
            float su = (float)(wlo - 1 + j);
            float F = 0.f;
            #pragma unroll
            for (int m = 0; m < MM; ++m)
                F += sm.alpha[m] * sig_tanh((su + 1.5f - sm.ksi[m]) * sm.rbeta[m]);
            sm.u.pb.Fbuf[j] = F;
        }
        __syncthreads();

        // w[s] = F(s) - F(s-1) inside window, else 0; write alignment
        {
            int s = tid;                               // 0..511
            float w = 0.f;
            if (s >= wlo && s < whi)
                w = sm.u.pb.Fbuf[s - wlo + 1] - sm.u.pb.Fbuf[s - wlo];
            sm.wbuf[s] = w;
            if (dg == 0) out[ALIGN_OFF + ((size_t)b * TT + t) * SS + s] = w;
        }
        // termination (last step): exact exp-based formula on its one element
        if (t == TT - 1 && dg == 0 && tid == 0) {
            float su = (float)(lens[b] - 1);
            float t1 = 0.f;
            #pragma unroll
            for (int m = 0; m < MM; ++m)
                t1 += sm.alpha[m] * sigf((su + 1.5f - sm.ksi[m]) * sm.rbeta[m]);
            out[TERM_OFF + b] = 1.f - t1;
        }
        __syncthreads();

        // ================= Phase C : ctx = w @ memory (windowed, 16 warps) =====
        {
            float accv[8];
            #pragma unroll
            for (int j = 0; j < 8; ++j) accv[j] = 0.f;
            const __half* mpb = g_mem + (size_t)b * SS * DD + dg * 256 + lane * 8;
            for (int s0 = wlo + wid; s0 < whi; s0 += 64) {
                uint4 v[4]; float wv[4];
                #pragma unroll
                for (int j = 0; j < 4; ++j) {
                    int s = s0 + 16 * j;
                    if (s < whi) {
                        v[j]  = __ldg((const uint4*)(mpb + (size_t)s * DD));
                        wv[j] = sm.wbuf[s];
                    }
                }
                #pragma unroll
                for (int j = 0; j < 4; ++j) {
                    int s = s0 + 16 * j;
                    if (s < whi) {
                        const __half2* h2 = (const __half2*)&v[j];
                        #pragma unroll
                        for (int q = 0; q < 4; ++q) {
                            float2 f = __half22float2(h2[q]);
                            accv[2 * q]     += wv[j] * f.x;
                            accv[2 * q + 1] += wv[j] * f.y;
                        }
                    }
                }
            }
            float* cr = sm.u.cred[wid];
            #pragma unroll
            for (int j = 0; j < 8; ++j) cr[lane * 8 + j] = accv[j];
        }
        __syncthreads();
        if (tid < 256) {
            int d = tid;                       // 0..255 within this CTA's d-slice
            float s0 = 0.f;
            #pragma unroll
            for (int w = 0; w < 16; ++w) s0 += sm.u.cred[w][d];
            g_ctx[b * DD + dg * 256 + d] = __float2half(s0);
            if (t == TT - 1) out[b * DD + dg * 256 + d] = s0;
        }
        __syncthreads();
        if (tid == 0) {
            __threadfence();
            atomicAdd(&g_cctr, 1u);            // phase-C completion (replaces barrier2)
        }
    }
}

extern "C" void kernel_launch(void* const* d_in, const int* in_sizes, int n_in,
                              void* d_out, int out_size) {
    const float* in_h   = (const float*)d_in[0];
    const float* mem    = (const float*)d_in[1];
    const int*   lens   = (const int*)d_in[2];
    const float* W_ih   = (const float*)d_in[3];
    const float* W_hh   = (const float*)d_in[4];
    const float* b_ih   = (const float*)d_in[5];
    const float* b_hh   = (const float*)d_in[6];
    const float* W_g    = (const float*)d_in[7];
    const float* b_g    = (const float*)d_in[8];
    float* out = (float*)d_out;

    cudaFuncSetAttribute(tts_main, cudaFuncAttributeMaxDynamicSharedMemorySize,
                         (int)sizeof(Smem));

    tts_prep<<<1024, 256>>>(in_h, mem);
    tts_main<<<NCTA, NTHR, sizeof(Smem)>>>(W_ih, W_hh, b_ih, b_hh, W_g, b_g, lens, out);
}

// round 11
// speedup vs baseline: 1.3251x; 1.0657x over previous
#include <cuda_runtime.h>
#include <cuda_fp16.h>
#include <math.h>
#include <stdint.h>

#define BB   32
#define TT   512
#define SS   512
#define DD   1024
#define MM   10
#define K3   3072
#define KP   3080      // padded K stride (halves) for Ws: conflict-free B-frag loads
#define NCTA 128
#define NTHR 512

// ---------------- static device scratch (allocations are forbidden) ----------------
__device__ __half  g_in[BB * TT * DD];          // fp16 copy of input_h_c
__device__ __half  g_mem[BB * SS * DD];         // fp16 copy of memory
__device__ __half  g_ctx[BB * DD];              // ctx_t (fp16), produced by phase C
__device__ __half  g_h[2][BB * DD];             // double-buffered h (fp16)
__device__ float   g_phipart[2][NCTA][BB][32];  // per-CTA phi partials, dbl-buffered
__device__ __align__(128) unsigned g_cctr;      // phase-C completion counter (monotonic)
__device__ __align__(128) unsigned g_phictr;    // phi publication counter (monotonic)

// ---------------- dynamic shared memory layout ----------------
struct Smem {
    __half Ws[32][KP];                 // persistent weight slice     197120 B
    union {
        __half xsw[16][2][16][24];     // per-warp x staging (k16)    24576 B
        float  redA[4][2][16][33];     // K-split reduction (2-pass)  16896 B
        float  cred[16][256];          // phase-C cross-warp reduce   16384 B
        struct {                       // phase-B scratch
            float Fbuf[520];           // windowed CDF
            float predbuf[8][32];      // phi reduce stage
            float phired[32];          // reduced phi
        } pb;
    } u;
    float gates[32][32];               // reduced gate tile             4096 B
    float cst[32][8];                  // persistent cell state         1024 B
    float hs[32][8];                   // fp32 h slice                  1024 B
    float Wg[32][8];                   // W_g slice (30 used)           1024 B
    float biasv[32];                   // b_ih + b_hh per local col      128 B
    float bgs[32];                     // b_g (30 used)                  128 B
    float wbuf[SS];                    // attention weights              2048 B
    float ksi[16];                     // persistent ksi                   64 B
    float rbeta[16];                   // 1/beta                           64 B
    float alpha[16];                   // softmax alpha                    64 B
    int   winlo, winhi;                // phase-C / CDF window             8 B
};

// ---------------- prep: fp32 -> fp16 conversions + state reset ----------------
__global__ void tts_prep(const float* __restrict__ in, const float* __restrict__ mem) {
    const int tid = blockIdx.x * blockDim.x + threadIdx.x;
    const int np  = gridDim.x * blockDim.x;
    const int N1  = BB * TT * DD;
    for (int i = tid; i < N1; i += np) g_in[i]  = __float2half(in[i]);
    for (int i = tid; i < N1; i += np) g_mem[i] = __float2half(mem[i]);
    for (int i = tid; i < BB * DD; i += np) {
        g_ctx[i]  = __float2half(0.f);
        g_h[0][i] = __float2half(0.f);
        g_h[1][i] = __float2half(0.f);
    }
    if (tid == 0) { g_cctr = 0u; g_phictr = 0u; }
}

#define MMA_16816(ac, A0, A1, A2, A3, B0, B1)                               \
    asm volatile(                                                           \
        "mma.sync.aligned.m16n8k16.row.col.f32.f16.f16.f32 "                \
        "{%0,%1,%2,%3}, {%4,%5,%6,%7}, {%8,%9}, {%0,%1,%2,%3};"             \
        : "+f"((ac)[0]), "+f"((ac)[1]), "+f"((ac)[2]), "+f"((ac)[3])        \
        : "r"(A0), "r"(A1), "r"(A2), "r"(A3), "r"(B0), "r"(B1))

__device__ __forceinline__ float sigf(float x) {          // accurate (2 MUFU)
    return __fdividef(1.f, 1.f + __expf(-x));
}
__device__ __forceinline__ float sig_tanh(float z) {      // fast (1 MUFU)
    float t;
    asm("tanh.approx.f32 %0, %1;" : "=f"(t) : "f"(z * 0.5f));
    return fmaf(t, 0.5f, 0.5f);
}

// seq index (0..23) -> perm value: 8 x-chunks, 8 h-chunks, then 8 ctx-chunks
__device__ __forceinline__ int permv(int i) {
    return (i < 8) ? i : ((i < 16) ? i + 8 : i - 8);
}

// ---------------- main persistent kernel ----------------
__global__ void __launch_bounds__(NTHR, 1) tts_main(
    const float* __restrict__ W_ih, const float* __restrict__ W_hh,
    const float* __restrict__ b_ih, const float* __restrict__ b_hh,
    const float* __restrict__ W_g,  const float* __restrict__ b_g,
    const int*   __restrict__ lens, float* __restrict__ out)
{
    extern __shared__ char smraw[];
    Smem& sm = *reinterpret_cast<Smem*>(smraw);
    const int tid  = threadIdx.x;
    const int cta  = blockIdx.x;
    const int wid  = tid >> 5;
    const int lane = tid & 31;

    const size_t ALIGN_OFF = (size_t)BB * DD;                      // 32768
    const size_t TERM_OFF  = ALIGN_OFF + (size_t)BB * TT * SS;     // 8421376

    // ---- one-time init ----
    for (int i = tid; i < 32 * K3; i += NTHR) {
        int c = i / K3, k = i - c * K3;
        int gcol = (c >> 3) * DD + cta * 8 + (c & 7);
        float wv = (k < 2048) ? W_ih[(size_t)gcol * 2048 + k]
                              : W_hh[(size_t)gcol * DD + (k - 2048)];
        sm.Ws[c][k] = __float2half(wv);
    }
    if (tid < 240) {
        int j = tid >> 3, uu = tid & 7;
        sm.Wg[j][uu] = W_g[(size_t)j * DD + cta * 8 + uu];
    }
    if (tid < 32) {
        int gcol = (tid >> 3) * DD + cta * 8 + (tid & 7);
        sm.biasv[tid] = b_ih[gcol] + b_hh[gcol];
    }
    if (tid < 30) sm.bgs[tid] = b_g[tid];
    if (tid < 256) { int b2 = tid >> 3, uu = tid & 7; sm.cst[b2][uu] = 0.f; }
    if (tid < 16) { sm.ksi[tid] = 0.f; sm.rbeta[tid] = 0.f; sm.alpha[tid] = 0.f; }
    __syncthreads();

    // warp roles for the gate GEMM: 16 warps = (bt M-half) x (kw 8-way strided K)
    const int bt = wid & 1;          // batch-half (rows bt*16 .. +16)
    const int kw = wid >> 1;         // K stride class: chunks kw + 8*j
    const int gg = lane >> 2;        // mma group id (0..7)
    const int tg = lane & 3;         // thread-in-group (0..3)
    __half (&xw)[2][16][24] = sm.u.xsw[wid];
    const int xrow = lane >> 1;              // 0..15
    const int xb   = bt * 16 + xrow;         // global batch
    const int xo   = (lane & 1) * 8;         // half-offset within 16-half chunk

    // phase B/C roles
    const int b  = cta & 31;     // batch
    const int dg = cta >> 5;     // d-slice (0..3) of 256

    for (int t = 0; t < TT; ++t) {
        const int p = t & 1;

        // ================= Phase A : gate GEMM =================
        float acc[16];
        #pragma unroll
        for (int i = 0; i < 16; ++i) acc[i] = 0.f;

        // seq i -> global k = 16*(kw + 8*permv(i)); x: pv<8, h: pv>=16, ctx: 8..15
        auto xsrc = [&](int i) -> const __half* {
            int pv = permv(i);
            int kk = 16 * kw + 128 * pv;
            if (pv < 8)  return g_in  + ((size_t)xb * TT + t) * DD + kk;
            if (pv >= 16) return g_h[p] + xb * DD + (kk - 2048);
            return g_ctx + xb * DD + (kk - 1024);
        };
        auto kglob = [&](int i) -> int { return 16 * kw + 128 * permv(i); };

        auto compute_chunk = [&](int buf, int i) {
            unsigned a0 = *(const unsigned*)&xw[buf][gg    ][2 * tg];
            unsigned a1 = *(const unsigned*)&xw[buf][gg + 8][2 * tg];
            unsigned a2 = *(const unsigned*)&xw[buf][gg    ][2 * tg + 8];
            unsigned a3 = *(const unsigned*)&xw[buf][gg + 8][2 * tg + 8];
            const int kg = kglob(i);
            #pragma unroll
            for (int nt = 0; nt < 4; ++nt) {
                unsigned b0 = *(const unsigned*)&sm.Ws[nt * 8 + gg][kg + 2 * tg];
                unsigned b1 = *(const unsigned*)&sm.Ws[nt * 8 + gg][kg + 2 * tg + 8];
                MMA_16816(acc + nt * 4, a0, a1, a2, a3, b0, b1);
            }
        };

        uint4 r0, r1;
        {   // prologue: seq0 -> buf0, seq1 -> r0, seq2 -> r1 (all x-chunks)
            uint4 ta = __ldcg((const uint4*)(xsrc(0) + xo));
            *(uint4*)&xw[0][xrow][xo] = ta;
            r0 = __ldcg((const uint4*)(xsrc(1) + xo));
            r1 = __ldcg((const uint4*)(xsrc(2) + xo));
        }
        __syncwarp();

        #pragma unroll 1
        for (int i = 0; i < 24; i += 2) {
            // even slot: compute seq i from buf0
            compute_chunk(0, i);
            *(uint4*)&xw[1][xrow][xo] = r0;          // stage seq i+1
            if (i + 3 < 24)                          // prefetch seq i+3
                r0 = __ldcg((const uint4*)(xsrc(i + 3) + xo));
            __syncwarp();
            // odd slot: compute seq i+1 from buf1
            compute_chunk(1, i + 1);
            if (i + 2 < 24)
                *(uint4*)&xw[0][xrow][xo] = r1;      // stage seq i+2
            if (i + 4 < 24) {
                if (i == 12) {
                    // seq 16 is the first ctx chunk: wait for all CTAs' phase C
                    // of step t-1. Lane 0 polls (32x less hot-line traffic),
                    // with backoff; __ldcg data reads are L2-coherent.
                    if (lane == 0) {
                        const unsigned want = (unsigned)(NCTA * t);
                        while (*(volatile unsigned*)&g_cctr < want) __nanosleep(64);
                    }
                    __syncwarp();
                }
                r1 = __ldcg((const uint4*)(xsrc(i + 4) + xo));
            }
            __syncwarp();
        }
        __syncthreads();

        // K-split reduction: two passes of 4 splits each (fp32, deterministic)
        #pragma unroll
        for (int pass = 0; pass < 2; ++pass) {
            if ((kw >> 2) == pass) {
                int ks = kw & 3;
                #pragma unroll
                for (int nt = 0; nt < 4; ++nt) {
                    #pragma unroll
                    for (int i = 0; i < 4; ++i) {
                        int r = gg + ((i >> 1) << 3);
                        int c = nt * 8 + tg * 2 + (i & 1);
                        sm.u.redA[ks][bt][r][c] = acc[nt * 4 + i];
                    }
                }
            }
            __syncthreads();
            #pragma unroll
            for (int rep = 0; rep < 2; ++rep) {
                int f = tid + rep * NTHR;              // 0..1023
                int bt2 = f >> 9, q = f & 511, r = q >> 5, c = q & 31;
                float v = sm.u.redA[0][bt2][r][c] + sm.u.redA[1][bt2][r][c]
                        + sm.u.redA[2][bt2][r][c] + sm.u.redA[3][bt2][r][c];
                if (pass == 0) sm.gates[bt2 * 16 + r][c] = v;
                else           sm.gates[bt2 * 16 + r][c] += v;
            }
            __syncthreads();
        }

        // ---- LSTM cell (thread = (batch, unit)) ----
        if (tid < 256) {
            int bb = tid >> 3, uu = tid & 7;
            float ig = sm.gates[bb][uu]      + sm.biasv[uu];
            float fg = sm.gates[bb][8 + uu]  + sm.biasv[8 + uu];
            float gv = sm.gates[bb][16 + uu] + sm.biasv[16 + uu];
            float og = sm.gates[bb][24 + uu] + sm.biasv[24 + uu];
            float cn = sigf(fg) * sm.cst[bb][uu] + sigf(ig) * tanhf(gv);
            sm.cst[bb][uu] = cn;
            float hv = sigf(og) * tanhf(cn);
            sm.hs[bb][uu] = hv;
            g_h[p ^ 1][bb * DD + cta * 8 + uu] = __float2half(hv);
        }
        __syncthreads();

        // ---- phi partials over this CTA's 8 units (double-buffered by t&1) ----
        #pragma unroll
        for (int it = 0; it < 2; ++it) {
            int idx = tid + it * NTHR;
            if (idx < 960) {
                int pb = idx / 30, j = idx - pb * 30;
                float s = 0.f;
                #pragma unroll
                for (int uu = 0; uu < 8; ++uu) s += sm.hs[pb][uu] * sm.Wg[j][uu];
                g_phipart[p][cta][pb][j] = s;
            }
        }

        // ---- phi counter barrier: RED + single-thread poll (no release hop) ----
        __syncthreads();
        if (tid == 0) {
            __threadfence();
            atomicAdd(&g_phictr, 1u);                      // publish phi(t) + h(t)
            const unsigned want = (unsigned)(NCTA * (t + 1));
            while (*(volatile unsigned*)&g_phictr < want) __nanosleep(64);
            __threadfence();
        }
        __syncthreads();

        // ================= Phase B : mixture head (batch b) =================
        if (tid < 240) {
            int j = tid % 30, cg = tid / 30;
            float s = 0.f;
            int c0 = cg * 16;
            #pragma unroll
            for (int c = 0; c < 16; ++c) s += __ldcg(&g_phipart[p][c0 + c][b][j]);
            sm.u.pb.predbuf[cg][j] = s;
        }
        __syncthreads();
        if (tid < 30) {
            float s = sm.bgs[tid];
            #pragma unroll
            for (int cg = 0; cg < 8; ++cg) s += sm.u.pb.predbuf[cg][tid];
            sm.u.pb.phired[tid] = s;
        }
        __syncthreads();

        // mixture params + dynamic window, parallel over 10 lanes of warp 0
        if (wid == 0) {
            float pha = (lane < MM) ? sm.u.pb.phired[20 + lane] : -1e30f;
            float mx = pha;
            #pragma unroll
            for (int off = 16; off >= 1; off >>= 1)
                mx = fmaxf(mx, __shfl_xor_sync(0xffffffffu, mx, off));
            float e = (lane < MM) ? __expf(pha - mx) : 0.f;
            float ssum = e;
            #pragma unroll
            for (int off = 16; off >= 1; off >>= 1)
                ssum += __shfl_xor_sync(0xffffffffu, ssum, off);
            float kv = 0.f, beta = 0.f;
            if (lane < MM) {
                float phb = sm.u.pb.phired[10 + lane];
                kv   = sm.ksi[lane] + __expf(sm.u.pb.phired[lane]);
                beta = __expf(phb);
                sm.ksi[lane]   = kv;
                sm.rbeta[lane] = __expf(-phb);
                sm.alpha[lane] = __fdividef(e, ssum);
            }
            float lof = (lane < MM) ? (kv - 14.f * beta - 1.5f) :  1e30f;
            float hif = (lane < MM) ? (kv + 14.f * beta + 0.5f) : -1e30f;
            #pragma unroll
            for (int off = 16; off >= 1; off >>= 1) {
                lof = fminf(lof, __shfl_xor_sync(0xffffffffu, lof, off));
                hif = fmaxf(hif, __shfl_xor_sync(0xffffffffu, hif, off));
            }
            if (lane == 0) {
                int lo = (int)floorf(lof); if (lo < 0) lo = 0; if (lo > SS) lo = SS;
                int hi = (int)ceilf(hif) + 1; if (hi > SS) hi = SS; if (hi < lo) hi = lo;
                sm.winlo = lo; sm.winhi = hi;
            }
        }
        __syncthreads();

        // ---- windowed telescoped CDF: Fbuf[j] = F(lo-1+j), j=0..n-1 ----
        const int wlo = sm.winlo, whi = sm.winhi;
        const int nF  = whi - wlo + 1;
        #pragma unroll 1
        for (int j = tid; j < nF; j += NTHR) {
            float su = (float)(wlo - 1 + j);
            float F = 0.f;
            #pragma unroll
            for (int m = 0; m < MM; ++m)
                F += sm.alpha[m] * sig_tanh((su + 1.5f - sm.ksi[m]) * sm.rbeta[m]);
            sm.u.pb.Fbuf[j] = F;
        }
        __syncthreads();

        // w[s] = F(s) - F(s-1) inside window, else 0; write alignment
        {
            int s = tid;                               // 0..511
            float w = 0.f;
            if (s >= wlo && s < whi)
                w = sm.u.pb.Fbuf[s - wlo + 1] - sm.u.pb.Fbuf[s - wlo];
            sm.wbuf[s] = w;
            if (dg == 0) out[ALIGN_OFF + ((size_t)b * TT + t) * SS + s] = w;
        }
        // termination (last step): exact exp-based formula on its one element
        if (t == TT - 1 && dg == 0 && tid == 0) {
            float su = (float)(lens[b] - 1);
            float t1 = 0.f;
            #pragma unroll
            for (int m = 0; m < MM; ++m)
                t1 += sm.alpha[m] * sigf((su + 1.5f - sm.ksi[m]) * sm.rbeta[m]);
            out[TERM_OFF + b] = 1.f - t1;
        }
        __syncthreads();

        // ================= Phase C : ctx = w @ memory (windowed, 16 warps) =====
        {
            float accv[8];
            #pragma unroll
            for (int j = 0; j < 8; ++j) accv[j] = 0.f;
            const __half* mpb = g_mem + (size_t)b * SS * DD + dg * 256 + lane * 8;
            for (int s0 = wlo + wid; s0 < whi; s0 += 64) {
                uint4 v[4]; float wv[4];
                #pragma unroll
                for (int j = 0; j < 4; ++j) {
                    int s = s0 + 16 * j;
                    if (s < whi) {
                        v[j]  = __ldg((const uint4*)(mpb + (size_t)s * DD));
                        wv[j] = sm.wbuf[s];
                    }
                }
                #pragma unroll
                for (int j = 0; j < 4; ++j) {
                    int s = s0 + 16 * j;
                    if (s < whi) {
                        const __half2* h2 = (const __half2*)&v[j];
                        #pragma unroll
                        for (int q = 0; q < 4; ++q) {
                            float2 f = __half22float2(h2[q]);
                            accv[2 * q]     += wv[j] * f.x;
                            accv[2 * q + 1] += wv[j] * f.y;
                        }
                    }
                }
            }
            float* cr = sm.u.cred[wid];
            #pragma unroll
            for (int j = 0; j < 8; ++j) cr[lane * 8 + j] = accv[j];
        }
        __syncthreads();
        if (tid < 256) {
            int d = tid;                       // 0..255 within this CTA's d-slice
            float s0 = 0.f;
            #pragma unroll
            for (int w = 0; w < 16; ++w) s0 += sm.u.cred[w][d];
            g_ctx[b * DD + dg * 256 + d] = __float2half(s0);
            if (t == TT - 1) out[b * DD + dg * 256 + d] = s0;
        }
        __syncthreads();
        if (tid == 0) {
            __threadfence();
            atomicAdd(&g_cctr, 1u);            // phase-C completion signal
        }
    }
}

extern "C" void kernel_launch(void* const* d_in, const int* in_sizes, int n_in,
                              void* d_out, int out_size) {
    const float* in_h   = (const float*)d_in[0];
    const float* mem    = (const float*)d_in[1];
    const int*   lens   = (const int*)d_in[2];
    const float* W_ih   = (const float*)d_in[3];
    const float* W_hh   = (const float*)d_in[4];
    const float* b_ih   = (const float*)d_in[5];
    const float* b_hh   = (const float*)d_in[6];
    const float* W_g    = (const float*)d_in[7];
    const float* b_g    = (const float*)d_in[8];
    float* out = (float*)d_out;

    cudaFuncSetAttribute(tts_main, cudaFuncAttributeMaxDynamicSharedMemorySize,
                         (int)sizeof(Smem));

    tts_prep<<<1024, 256>>>(in_h, mem);
    tts_main<<<NCTA, NTHR, sizeof(Smem)>>>(W_ih, W_hh, b_ih, b_hh, W_g, b_g, lens, out);
}